// round 5
// baseline (speedup 1.0000x reference)
#include <cuda_runtime.h>
#include <cuda_bf16.h>
#include <mma.h>
#include <math.h>

using namespace nvcuda;

// Problem constants
#define BT   16     // batch
#define CH   1024   // channels
#define HW   48     // height/width
#define SP   24     // spatial tile
#define SS   576    // spatial area
#define HD   72     // mlp hidden
#define BB   64     // chunk batches (4 tiles * 16)
#define BLK  512    // channel block size
#define KTAY 12     // Taylor terms for exp(2ab)
#define JJ   24     // 2 blocks * KTAY

// ---------------- scratch (__device__ globals; no runtime alloc) ----------------
__device__ __align__(16) float g_H [BB*HD*CH];     // relu(W1_in . X)   (b,o,c)
__device__ __align__(16) float g_H2[BB*HD*CH];     // relu(W1_out . Z)  (b,o,d)
__device__ __align__(16) float g_xm[BB*CH];
__device__ __align__(16) float g_u [BB*CH];        // exp(-xm^2)
__device__ __align__(16) float g_t [BB*JJ];        // moments sum_c u*xm^k per (b,blk)
__device__ __align__(16) float g_T [BB*HD*JJ];     // H . Omega
__device__ __align__(16) float g_M2[HD*HD];        // W1_out . W2_in
__device__ __align__(16) float g_wv[HD];           // W1_out . b2_in
__device__ __align__(16) float g_mw2[HD];          // colmean(W2_in)
__device__ float g_mb2;
__device__ __align__(16) float g_G [HD*HD];        // Gram of H2
__device__ __align__(16) float g_hs[HD];           // sum of H2
__device__ __align__(16) float g_a [SS];           // 0.25*rsig*gamma
__device__ __align__(16) float g_bsh[SS];          // 0.25*(beta + a*(bias - mu))

// ---------------- kz: zero accumulators ----------------
__global__ void kz() {
    int t = threadIdx.x;
    for (int i = t; i < HD*HD; i += 512) g_G[i] = 0.f;
    if (t < HD) g_hs[t] = 0.f;
}

// ---------------- kp2: column means of W2_in ----------------
__global__ void kp2(const float* __restrict__ w2i, const float* __restrict__ b2i) {
    int t = threadIdx.x;
    if (t < HD) {
        float a = 0.f;
        for (int s = 0; s < SS; s++) a += w2i[s*HD + t];
        g_mw2[t] = a * (1.f/SS);
    }
    if (t == 600) {
        float a = 0.f;
        for (int s = 0; s < SS; s++) a += b2i[s];
        g_mb2 = a * (1.f/SS);
    }
}

// ---------------- kp1: M2 = W1_out.W2_in, wv = W1_out.b2_in ----------------
__global__ void kp1(const float* __restrict__ w1o, const float* __restrict__ w2i,
                    const float* __restrict__ b2i) {
    int o = blockIdx.x, o2 = threadIdx.x;
    float acc = 0.f;
    for (int s = 0; s < SS; s++) acc = fmaf(w1o[o*SS + s], w2i[s*HD + o2], acc);
    g_M2[o*HD + o2] = acc;
    if (o2 == 0) {
        float a2 = 0.f;
        for (int s = 0; s < SS; s++) a2 = fmaf(w1o[o*SS + s], b2i[s], a2);
        g_wv[o] = a2;
    }
}

// ---------------- K1: H = relu(W_in1 . Xg + b_in1) via tf32 wmma; fused xm ----------------
__global__ __launch_bounds__(256) void k1_mma(const float* __restrict__ x,
        const float* __restrict__ w1, const float* __restrict__ b1) {
    __shared__ __align__(16) float smbuf[80*136];   // 43520 B
    float* As = smbuf;                // [80][52]
    float* Bs = smbuf + 80*52;        // [128][52]
    float* Cs = smbuf;                // [80][136] (aliases after loop)
    int tid = threadIdx.x, w = tid >> 5;
    int n0 = blockIdx.x << 7;
    int b = n0 >> 10, c0 = n0 & 1023;
    int chunk = b >> 4, bt = b & 15;
    int ty = (chunk >> 1) * SP, tx = (chunk & 1) * SP;
    const float* xb = x + (size_t)(bt*CH + c0) * 2304 + ty*48 + tx;

    wmma::fragment<wmma::accumulator,16,16,8,float> acc[5];
#pragma unroll
    for (int i = 0; i < 5; i++) wmma::fill_fragment(acc[i], 0.f);

    for (int kc = 0; kc < 12; ++kc) {
        int k0 = kc * 48;
        for (int idx = tid; idx < 80*48; idx += 256) {
            int o = idx / 48, kk = idx - o*48;
            As[o*52 + kk] = (o < HD) ? w1[o*SS + k0 + kk] : 0.f;
        }
        int sy0 = kc * 2;
        for (int q = tid; q < 128*12; q += 256) {
            int c = q / 12, qs = q - c*12;
            int row = (qs >= 6) ? 1 : 0;
            int sxx = (qs - row*6) * 4;
            float4 v = *(const float4*)(xb + (size_t)c*2304 + (sy0+row)*48 + sxx);
            *(float4*)&Bs[c*52 + row*24 + sxx] = v;
        }
        __syncthreads();
#pragma unroll
        for (int k8 = 0; k8 < 6; ++k8) {
            wmma::fragment<wmma::matrix_b,16,16,8,wmma::precision::tf32,wmma::col_major> bf;
            wmma::load_matrix_sync(bf, Bs + (w*16)*52 + k8*8, 52);
#pragma unroll
            for (int e = 0; e < bf.num_elements; e++) bf.x[e] = wmma::__float_to_tf32(bf.x[e]);
#pragma unroll
            for (int i = 0; i < 5; ++i) {
                wmma::fragment<wmma::matrix_a,16,16,8,wmma::precision::tf32,wmma::row_major> af;
                wmma::load_matrix_sync(af, As + (i*16)*52 + k8*8, 52);
#pragma unroll
                for (int e = 0; e < af.num_elements; e++) af.x[e] = wmma::__float_to_tf32(af.x[e]);
                wmma::mma_sync(acc[i], af, bf, acc[i]);
            }
        }
        __syncthreads();
    }
#pragma unroll
    for (int i = 0; i < 5; ++i)
        wmma::store_matrix_sync(Cs + (i*16)*136 + w*16, acc[i], 136, wmma::mem_row_major);
    __syncthreads();
    for (int idx = tid; idx < 72*32; idx += 256) {
        int o = idx >> 5, cq = (idx & 31) << 2;
        float bias = __ldg(&b1[o]);
        float4 v = *(float4*)&Cs[o*136 + cq];
        v.x = fmaxf(v.x + bias, 0.f); v.y = fmaxf(v.y + bias, 0.f);
        v.z = fmaxf(v.z + bias, 0.f); v.w = fmaxf(v.w + bias, 0.f);
        *(float4*)&g_H[(size_t)(b*HD + o)*CH + c0 + cq] = v;
    }
    if (tid < 128) {
        int c = tid;
        float a = g_mb2;
#pragma unroll 8
        for (int o = 0; o < HD; o++) {
            float h = fmaxf(Cs[o*136 + c] + __ldg(&b1[o]), 0.f);
            a = fmaf(g_mw2[o], h, a);
        }
        g_xm[b*CH + c0 + c] = a;
        g_u [b*CH + c0 + c] = expf(-a*a);
    }
}

// ---------------- K34: T (and moments t as ones-row) ----------------
// rows o=0..71 : T[b,o,(blk,k)] = sum_c H*u*xm^k ; row o=72 (H==1): t_k
__global__ __launch_bounds__(896) void k34() {
    int bb = blockIdx.x; int b = bb >> 1, blk = bb & 1;
    int tid = threadIdx.x;
    int o = tid / KTAY, k = tid - o*KTAY;   // valid for tid < 876
    __shared__ float Hs[73][65];
    __shared__ float ws[KTAY][66];
    float acc = 0.f;
    for (int c0 = 0; c0 < BLK; c0 += 64) {
        if (tid < KTAY*64) {
            int kk = tid >> 6, cc = tid & 63;
            int c = b*CH + blk*BLK + c0 + cc;
            float xm = g_xm[c], pw = g_u[c];
            for (int t = 0; t < kk; t++) pw *= xm;
            ws[kk][cc] = pw;
        }
        for (int idx = tid; idx < 73*64; idx += 896) {
            int o2 = idx >> 6, cc = idx & 63;
            Hs[o2][cc] = (o2 < HD) ? g_H[(size_t)(b*HD + o2)*CH + blk*BLK + c0 + cc] : 1.f;
        }
        __syncthreads();
        if (tid < 876) {
#pragma unroll
            for (int cc = 0; cc < 64; cc++) acc = fmaf(Hs[o][cc], ws[k][cc], acc);
        }
        __syncthreads();
    }
    if (tid < 876) {
        if (o < HD) g_T[(b*HD + o)*JJ + blk*KTAY + k] = acc;
        else        g_t[bb*KTAY + k] = acc;
    }
}

// ---------------- K56: R (in smem, redundant per block) then H2 ----------------
__global__ __launch_bounds__(128) void k56(const float* __restrict__ b1o) {
    int b = blockIdx.y;
    int d = blockIdx.x * 128 + threadIdx.x;
    int blk = d >> 9;
    int tid = threadIdx.x;
    __shared__ float Ts[HD*JJ];
    __shared__ float Rs[HD*JJ];
    __shared__ float tb[JJ];
    __shared__ float bo[HD];
    for (int idx = tid; idx < HD*JJ; idx += 128) Ts[idx] = g_T[b*HD*JJ + idx];
    if (tid < JJ) tb[tid] = g_t[b*JJ + tid];
    if (tid < HD) bo[tid] = b1o[tid];
    __syncthreads();
    for (int idx = tid; idx < HD*JJ; idx += 128) {
        int o = idx / JJ, jj = idx - o*JJ;
        float acc = g_wv[o] * tb[jj];
#pragma unroll 8
        for (int o2 = 0; o2 < HD; o2++)
            acc = fmaf(g_M2[o*HD + o2], Ts[o2*JJ + jj], acc);
        Rs[idx] = acc;
    }
    __syncthreads();
    float xm = g_xm[b*CH + d];
    float p[KTAY];
    p[0] = 1.f;
#pragma unroll
    for (int k = 1; k < KTAY; k++) p[k] = p[k-1] * (2.f * xm / (float)k);
    float denom = 0.f;
#pragma unroll
    for (int k = 0; k < KTAY; k++) denom = fmaf(p[k], tb[blk*KTAY + k], denom);
    float inv = 1.0f / denom;
    for (int o = 0; o < HD; o++) {
        float acc = 0.f;
#pragma unroll
        for (int k = 0; k < KTAY; k++) acc = fmaf(Rs[o*JJ + blk*KTAY + k], p[k], acc);
        g_H2[(size_t)(b*HD + o)*CH + d] = fmaxf(fmaf(acc, inv, bo[o]), 0.f);
    }
}

// ---------------- K6g: Gram G = sum H2 H2^T, hsum = sum H2 ----------------
__global__ __launch_bounds__(288) void k6g() {
    int blk = blockIdx.x;
    int b = blk >> 1, c0 = (blk & 1) << 9;
    int tid = threadIdx.x;
    int i0 = (tid % 24) * 3, j0 = (tid / 24) * 6;
    __shared__ float Hs[HD][65];
    float acc[3][6];
#pragma unroll
    for (int i = 0; i < 3; i++)
#pragma unroll
        for (int j = 0; j < 6; j++) acc[i][j] = 0.f;
    float hs = 0.f;
    for (int cc0 = 0; cc0 < 512; cc0 += 64) {
        for (int idx = tid; idx < HD*64; idx += 288) {
            int o = idx >> 6, cc = idx & 63;
            Hs[o][cc] = g_H2[(size_t)(b*HD + o)*CH + c0 + cc0 + cc];
        }
        __syncthreads();
        if (tid < HD) {
#pragma unroll 16
            for (int cc = 0; cc < 64; cc++) hs += Hs[tid][cc];
        }
#pragma unroll 4
        for (int cc = 0; cc < 64; cc++) {
            float a0 = Hs[i0][cc], a1 = Hs[i0+1][cc], a2 = Hs[i0+2][cc];
#pragma unroll
            for (int jj = 0; jj < 6; ++jj) {
                float bv = Hs[j0+jj][cc];
                acc[0][jj] = fmaf(a0, bv, acc[0][jj]);
                acc[1][jj] = fmaf(a1, bv, acc[1][jj]);
                acc[2][jj] = fmaf(a2, bv, acc[2][jj]);
            }
        }
        __syncthreads();
    }
#pragma unroll
    for (int ii = 0; ii < 3; ii++)
#pragma unroll
        for (int jj = 0; jj < 6; jj++)
            atomicAdd(&g_G[(i0+ii)*HD + j0+jj], acc[ii][jj]);
    if (tid < HD) atomicAdd(&g_hs[tid], hs);
}

// ---------------- K8b: analytic BN stats per s -> folded affine ----------------
__global__ __launch_bounds__(128) void k8b(const float* __restrict__ w2o,
        const float* __restrict__ b2o, const float* __restrict__ gamma,
        const float* __restrict__ beta) {
    int s = blockIdx.x, t = threadIdx.x;
    __shared__ float rq[128], rd[128];
    float q = 0.f, d = 0.f;
    if (t < HD) {
        float wt = w2o[s*HD + t];
        float v = 0.f;
        for (int o2 = 0; o2 < HD; ++o2)
            v = fmaf(g_G[t*HD + o2], w2o[s*HD + o2], v);
        q = wt * v;
        d = wt * g_hs[t];
    }
    rq[t] = q; rd[t] = d;
    __syncthreads();
    for (int st = 64; st > 0; st >>= 1) {
        if (t < st) { rq[t] += rq[t+st]; rd[t] += rd[t+st]; }
        __syncthreads();
    }
    if (t == 0) {
        const float N = (float)(BB*CH);
        float bias = b2o[s];
        float dot = rd[0];
        float mu = dot / N + bias;
        float esq = rq[0]/N + 2.f*bias*dot/N + bias*bias;
        float var = esq - mu*mu;
        float a = rsqrtf(var + 1e-5f) * gamma[s];
        g_a  [s] = 0.25f * a;
        g_bsh[s] = 0.25f * (beta[s] + a*(bias - mu));
    }
}

// ---------------- K7f: O = W2o.H2 (tf32) + BN + scatter + relu, N=32/block ----------------
__global__ __launch_bounds__(384) void k7f(const float* __restrict__ w2o,
        const float* __restrict__ x, float* __restrict__ out) {
    __shared__ __align__(16) float Bs[HD*36];    // [o][c] pitch 36
    __shared__ __align__(16) float Os[32*96];    // [c][sl] pitch 96
    int tid = threadIdx.x, w = tid >> 5;
    int n0 = blockIdx.x << 5;
    int b = n0 >> 10, c0 = n0 & 1023;

    for (int idx = tid; idx < HD*32; idx += 384) {
        int o = idx >> 5, c = idx & 31;
        Bs[o*36 + c] = g_H2[(size_t)(b*HD + o)*CH + c0 + c];
    }
    __syncthreads();

    wmma::fragment<wmma::accumulator,16,16,8,float> acc[3][2];
#pragma unroll
    for (int j = 0; j < 3; j++)
#pragma unroll
        for (int cf = 0; cf < 2; cf++) wmma::fill_fragment(acc[j][cf], 0.f);

#pragma unroll
    for (int k8 = 0; k8 < 9; ++k8) {
        wmma::fragment<wmma::matrix_b,16,16,8,wmma::precision::tf32,wmma::row_major> bf[2];
#pragma unroll
        for (int cf = 0; cf < 2; cf++) {
            wmma::load_matrix_sync(bf[cf], Bs + (k8*8)*36 + cf*16, 36);
#pragma unroll
            for (int e = 0; e < bf[cf].num_elements; e++)
                bf[cf].x[e] = wmma::__float_to_tf32(bf[cf].x[e]);
        }
#pragma unroll
        for (int j = 0; j < 3; ++j) {
            wmma::fragment<wmma::matrix_a,16,16,8,wmma::precision::tf32,wmma::row_major> af;
            wmma::load_matrix_sync(af, w2o + (size_t)((w + 12*j)*16)*HD + k8*8, HD);
#pragma unroll
            for (int e = 0; e < af.num_elements; e++)
                af.x[e] = wmma::__float_to_tf32(af.x[e]);
#pragma unroll
            for (int cf = 0; cf < 2; cf++)
                wmma::mma_sync(acc[j][cf], af, bf[cf], acc[j][cf]);
        }
    }

    int chunk = b >> 4, bt = b & 15;
    int ty = (chunk >> 1)*SP, tx = (chunk & 1)*SP;
    const float* xb = x   + (size_t)(bt*CH + c0)*2304 + ty*48 + tx;
    float*       ob = out + (size_t)(bt*CH + c0)*2304 + ty*48 + tx;

    for (int p = 0; p < 6; ++p) {
        __syncthreads();
        if ((w < 6) == ((p & 1) == 0)) {
            int j  = p >> 1;
            int wl = w - 6*(p & 1);
#pragma unroll
            for (int cf = 0; cf < 2; ++cf)
                wmma::store_matrix_sync(Os + (cf*16)*96 + wl*16, acc[j][cf], 96,
                                        wmma::mem_col_major);
        }
        __syncthreads();
        int sy0 = p*4;
        for (int idx = tid; idx < 768; idx += 384) {
            int sx4 = idx % 6;
            int t2  = idx / 6;
            int syl = t2 & 3;
            int c   = t2 >> 2;
            int sl  = syl*24 + sx4*4;
            int s0  = p*96 + sl;
            float4 v  = *(float4*)&Os[c*96 + sl];
            float4 av = *(const float4*)&g_a[s0];
            float4 bv = *(const float4*)&g_bsh[s0];
            size_t ga = (size_t)c*2304 + (sy0+syl)*48 + sx4*4;
            float4 xv = *(const float4*)(xb + ga);
            float4 r;
            r.x = fmaxf(xv.x + fmaf(v.x, av.x, bv.x), 0.f);
            r.y = fmaxf(xv.y + fmaf(v.y, av.y, bv.y), 0.f);
            r.z = fmaxf(xv.z + fmaf(v.z, av.z, bv.z), 0.f);
            r.w = fmaxf(xv.w + fmaf(v.w, av.w, bv.w), 0.f);
            *(float4*)(ob + ga) = r;
        }
    }
}

// ---------------- launch ----------------
extern "C" void kernel_launch(void* const* d_in, const int* in_sizes, int n_in,
                              void* d_out, int out_size) {
    (void)in_sizes; (void)n_in; (void)out_size;
    const float* x      = (const float*)d_in[0];
    const float* w_in1  = (const float*)d_in[1];
    const float* b_in1  = (const float*)d_in[2];
    const float* w_in2  = (const float*)d_in[3];
    const float* b_in2  = (const float*)d_in[4];
    const float* w_out1 = (const float*)d_in[5];
    const float* b_out1 = (const float*)d_in[6];
    const float* w_out2 = (const float*)d_in[7];
    const float* b_out2 = (const float*)d_in[8];
    const float* gamma  = (const float*)d_in[9];
    const float* beta   = (const float*)d_in[10];
    float* out = (float*)d_out;

    kz <<<1, 512>>>();                                   // 1
    kp2<<<1, 640>>>(w_in2, b_in2);                       // 2
    kp1<<<HD, HD>>>(w_out1, w_in2, b_in2);               // 3
    k1_mma<<<(BB*CH)/128, 256>>>(x, w_in1, b_in1);       // 4  <- profiled slot
    k34<<<BB*2, 896>>>();                                // 5
    k56<<<dim3(CH/128, BB), 128>>>(b_out1);              // 6
    k6g<<<BB*2, 288>>>();                                // 7
    k8b<<<SS, 128>>>(w_out2, b_out2, gamma, beta);       // 8
    k7f<<<(BB*CH)/32, 384>>>(w_out2, x, out);            // 9
}

// round 6
// speedup vs baseline: 1.0487x; 1.0487x over previous
#include <cuda_runtime.h>
#include <cuda_bf16.h>
#include <mma.h>
#include <math.h>

using namespace nvcuda;

// Problem constants
#define BT   16     // batch
#define CH   1024   // channels
#define HW   48     // height/width
#define SP   24     // spatial tile
#define SS   576    // spatial area
#define HD   72     // mlp hidden
#define BB   64     // chunk batches (4 tiles * 16)
#define BLK  512    // channel block size
#define KTAY 12     // Taylor terms for exp(2ab)
#define JJ   24     // 2 blocks * KTAY

// ---------------- scratch (__device__ globals; no runtime alloc) ----------------
__device__ __align__(16) float g_H [BB*HD*CH];     // relu(W1_in . X)   (b,o,c)
__device__ __align__(16) float g_H2[BB*HD*CH];     // relu(W1_out . Z)  (b,o,d)
__device__ __align__(16) float g_xm[BB*CH];
__device__ __align__(16) float g_u [BB*CH];        // exp(-xm^2)
__device__ __align__(16) float g_t [BB*JJ];        // moments sum_c u*xm^k per (b,blk)
__device__ __align__(16) float g_T [BB*HD*JJ];     // H . Omega
__device__ __align__(16) float g_M2[HD*HD];        // W1_out . W2_in
__device__ __align__(16) float g_wv[HD];           // W1_out . b2_in
__device__ __align__(16) float g_mw2[HD];          // colmean(W2_in)
__device__ float g_mb2;
__device__ __align__(16) float g_G [HD*HD];        // Gram of H2
__device__ __align__(16) float g_hs[HD];           // sum of H2
__device__ __align__(16) float g_a [SS];           // 0.25*rsig*gamma
__device__ __align__(16) float g_bsh[SS];          // 0.25*(beta + a*(bias - mu))

__device__ __forceinline__ float tf32r(float v) { return wmma::__float_to_tf32(v); }

// ---------------- kz: zero accumulators ----------------
__global__ void kz() {
    int t = threadIdx.x;
    for (int i = t; i < HD*HD; i += 512) g_G[i] = 0.f;
    if (t < HD) g_hs[t] = 0.f;
}

// ---------------- kp2: column means of W2_in ----------------
__global__ void kp2(const float* __restrict__ w2i, const float* __restrict__ b2i) {
    int t = threadIdx.x;
    if (t < HD) {
        float a = 0.f;
        for (int s = 0; s < SS; s++) a += w2i[s*HD + t];
        g_mw2[t] = a * (1.f/SS);
    }
    if (t == 600) {
        float a = 0.f;
        for (int s = 0; s < SS; s++) a += b2i[s];
        g_mb2 = a * (1.f/SS);
    }
}

// ---------------- kp1: M2 = W1_out.W2_in, wv = W1_out.b2_in ----------------
__global__ void kp1(const float* __restrict__ w1o, const float* __restrict__ w2i,
                    const float* __restrict__ b2i) {
    int o = blockIdx.x, o2 = threadIdx.x;
    float acc = 0.f;
    for (int s = 0; s < SS; s++) acc = fmaf(w1o[o*SS + s], w2i[s*HD + o2], acc);
    g_M2[o*HD + o2] = acc;
    if (o2 == 0) {
        float a2 = 0.f;
        for (int s = 0; s < SS; s++) a2 = fmaf(w1o[o*SS + s], b2i[s], a2);
        g_wv[o] = a2;
    }
}

// ---------------- K1: H = relu(W_in1 . Xg + b_in1) via tf32 wmma; fused xm ----------------
// 128 threads / 4 warps. Warp w owns n = [32w, 32w+32). acc[5][2].
// smem pre-rounded to tf32 at staging; NO per-fragment conversion.
__global__ __launch_bounds__(128) void k1_mma(const float* __restrict__ x,
        const float* __restrict__ w1, const float* __restrict__ b1) {
    __shared__ __align__(16) float smbuf[10880];   // 43520 B
    float* As = smbuf;                // [80][52]
    float* Bs = smbuf + 80*52;        // [128][52]
    float* Cs = smbuf;                // [80][136] (aliases after loop)
    int tid = threadIdx.x, w = tid >> 5;
    int n0 = blockIdx.x << 7;
    int b = n0 >> 10, c0 = n0 & 1023;
    int chunk = b >> 4, bt = b & 15;
    int ty = (chunk >> 1) * SP, tx = (chunk & 1) * SP;
    const float* xb = x + (size_t)(bt*CH + c0) * 2304 + ty*48 + tx;

    wmma::fragment<wmma::accumulator,16,16,8,float> acc[5][2];
#pragma unroll
    for (int i = 0; i < 5; i++)
#pragma unroll
        for (int cf = 0; cf < 2; cf++) wmma::fill_fragment(acc[i][cf], 0.f);

    for (int kc = 0; kc < 12; ++kc) {
        int k0 = kc * 48;
        // stage A: w1 rows (tf32-rounded), zero-pad o>=72
        for (int idx = tid; idx < 80*48; idx += 128) {
            int o = idx / 48, kk = idx - o*48;
            As[o*52 + kk] = (o < HD) ? tf32r(w1[o*SS + k0 + kk]) : 0.f;
        }
        // stage B as [c][k], tf32-rounded, float4 gmem loads
        int sy0 = kc * 2;
        for (int q = tid; q < 128*12; q += 128) {
            int c = q / 12, qs = q - c*12;
            int row = (qs >= 6) ? 1 : 0;
            int sxx = (qs - row*6) * 4;
            float4 v = *(const float4*)(xb + (size_t)c*2304 + (sy0+row)*48 + sxx);
            v.x = tf32r(v.x); v.y = tf32r(v.y); v.z = tf32r(v.z); v.w = tf32r(v.w);
            *(float4*)&Bs[c*52 + row*24 + sxx] = v;
        }
        __syncthreads();
#pragma unroll
        for (int k8 = 0; k8 < 6; ++k8) {
            wmma::fragment<wmma::matrix_b,16,16,8,wmma::precision::tf32,wmma::col_major> bf[2];
            wmma::load_matrix_sync(bf[0], Bs + (w*32     )*52 + k8*8, 52);
            wmma::load_matrix_sync(bf[1], Bs + (w*32 + 16)*52 + k8*8, 52);
#pragma unroll
            for (int i = 0; i < 5; ++i) {
                wmma::fragment<wmma::matrix_a,16,16,8,wmma::precision::tf32,wmma::row_major> af;
                wmma::load_matrix_sync(af, As + (i*16)*52 + k8*8, 52);
                wmma::mma_sync(acc[i][0], af, bf[0], acc[i][0]);
                wmma::mma_sync(acc[i][1], af, bf[1], acc[i][1]);
            }
        }
        __syncthreads();
    }
#pragma unroll
    for (int i = 0; i < 5; ++i)
#pragma unroll
        for (int cf = 0; cf < 2; ++cf)
            wmma::store_matrix_sync(Cs + (i*16)*136 + w*32 + cf*16, acc[i][cf], 136,
                                    wmma::mem_row_major);
    __syncthreads();
    for (int idx = tid; idx < 72*32; idx += 128) {
        int o = idx >> 5, cq = (idx & 31) << 2;
        float bias = __ldg(&b1[o]);
        float4 v = *(float4*)&Cs[o*136 + cq];
        v.x = fmaxf(v.x + bias, 0.f); v.y = fmaxf(v.y + bias, 0.f);
        v.z = fmaxf(v.z + bias, 0.f); v.w = fmaxf(v.w + bias, 0.f);
        *(float4*)&g_H[(size_t)(b*HD + o)*CH + c0 + cq] = v;
    }
    {
        int c = tid;
        float a = g_mb2;
#pragma unroll 8
        for (int o = 0; o < HD; o++) {
            float h = fmaxf(Cs[o*136 + c] + __ldg(&b1[o]), 0.f);
            a = fmaf(g_mw2[o], h, a);
        }
        g_xm[b*CH + c0 + c] = a;
        g_u [b*CH + c0 + c] = expf(-a*a);
    }
}

// ---------------- K34: T (and moments t as ones-row) ----------------
__global__ __launch_bounds__(896) void k34() {
    int bb = blockIdx.x; int b = bb >> 1, blk = bb & 1;
    int tid = threadIdx.x;
    int o = tid / KTAY, k = tid - o*KTAY;   // valid for tid < 876
    __shared__ float Hs[73][65];
    __shared__ float ws[KTAY][66];
    float acc = 0.f;
    for (int c0 = 0; c0 < BLK; c0 += 64) {
        if (tid < KTAY*64) {
            int kk = tid >> 6, cc = tid & 63;
            int c = b*CH + blk*BLK + c0 + cc;
            float xm = g_xm[c], pw = g_u[c];
            for (int t = 0; t < kk; t++) pw *= xm;
            ws[kk][cc] = pw;
        }
        for (int idx = tid; idx < 73*64; idx += 896) {
            int o2 = idx >> 6, cc = idx & 63;
            Hs[o2][cc] = (o2 < HD) ? g_H[(size_t)(b*HD + o2)*CH + blk*BLK + c0 + cc] : 1.f;
        }
        __syncthreads();
        if (tid < 876) {
#pragma unroll
            for (int cc = 0; cc < 64; cc++) acc = fmaf(Hs[o][cc], ws[k][cc], acc);
        }
        __syncthreads();
    }
    if (tid < 876) {
        if (o < HD) g_T[(b*HD + o)*JJ + blk*KTAY + k] = acc;
        else        g_t[bb*KTAY + k] = acc;
    }
}

// ---------------- K56: R (in smem, redundant per block) then H2 ----------------
__global__ __launch_bounds__(128) void k56(const float* __restrict__ b1o) {
    int b = blockIdx.y;
    int d = blockIdx.x * 128 + threadIdx.x;
    int blk = d >> 9;
    int tid = threadIdx.x;
    __shared__ float Ts[HD*JJ];
    __shared__ float Rs[HD*JJ];
    __shared__ float tb[JJ];
    __shared__ float bo[HD];
    for (int idx = tid; idx < HD*JJ; idx += 128) Ts[idx] = g_T[b*HD*JJ + idx];
    if (tid < JJ) tb[tid] = g_t[b*JJ + tid];
    if (tid < HD) bo[tid] = b1o[tid];
    __syncthreads();
    for (int idx = tid; idx < HD*JJ; idx += 128) {
        int o = idx / JJ, jj = idx - o*JJ;
        float acc = g_wv[o] * tb[jj];
#pragma unroll 8
        for (int o2 = 0; o2 < HD; o2++)
            acc = fmaf(g_M2[o*HD + o2], Ts[o2*JJ + jj], acc);
        Rs[idx] = acc;
    }
    __syncthreads();
    float xm = g_xm[b*CH + d];
    float p[KTAY];
    p[0] = 1.f;
#pragma unroll
    for (int k = 1; k < KTAY; k++) p[k] = p[k-1] * (2.f * xm / (float)k);
    float denom = 0.f;
#pragma unroll
    for (int k = 0; k < KTAY; k++) denom = fmaf(p[k], tb[blk*KTAY + k], denom);
    float inv = 1.0f / denom;
    for (int o = 0; o < HD; o++) {
        float acc = 0.f;
#pragma unroll
        for (int k = 0; k < KTAY; k++) acc = fmaf(Rs[o*JJ + blk*KTAY + k], p[k], acc);
        g_H2[(size_t)(b*HD + o)*CH + d] = fmaxf(fmaf(acc, inv, bo[o]), 0.f);
    }
}

// ---------------- K6g: Gram G = sum H2 H2^T, hsum = sum H2 ----------------
__global__ __launch_bounds__(288) void k6g() {
    int blk = blockIdx.x;
    int b = blk >> 1, c0 = (blk & 1) << 9;
    int tid = threadIdx.x;
    int i0 = (tid % 24) * 3, j0 = (tid / 24) * 6;
    __shared__ float Hs[HD][65];
    float acc[3][6];
#pragma unroll
    for (int i = 0; i < 3; i++)
#pragma unroll
        for (int j = 0; j < 6; j++) acc[i][j] = 0.f;
    float hs = 0.f;
    for (int cc0 = 0; cc0 < 512; cc0 += 64) {
        for (int idx = tid; idx < HD*64; idx += 288) {
            int o = idx >> 6, cc = idx & 63;
            Hs[o][cc] = g_H2[(size_t)(b*HD + o)*CH + c0 + cc0 + cc];
        }
        __syncthreads();
        if (tid < HD) {
#pragma unroll 16
            for (int cc = 0; cc < 64; cc++) hs += Hs[tid][cc];
        }
#pragma unroll 4
        for (int cc = 0; cc < 64; cc++) {
            float a0 = Hs[i0][cc], a1 = Hs[i0+1][cc], a2 = Hs[i0+2][cc];
#pragma unroll
            for (int jj = 0; jj < 6; ++jj) {
                float bv = Hs[j0+jj][cc];
                acc[0][jj] = fmaf(a0, bv, acc[0][jj]);
                acc[1][jj] = fmaf(a1, bv, acc[1][jj]);
                acc[2][jj] = fmaf(a2, bv, acc[2][jj]);
            }
        }
        __syncthreads();
    }
#pragma unroll
    for (int ii = 0; ii < 3; ii++)
#pragma unroll
        for (int jj = 0; jj < 6; jj++)
            atomicAdd(&g_G[(i0+ii)*HD + j0+jj], acc[ii][jj]);
    if (tid < HD) atomicAdd(&g_hs[tid], hs);
}

// ---------------- K8b: analytic BN stats per s -> folded affine ----------------
__global__ __launch_bounds__(128) void k8b(const float* __restrict__ w2o,
        const float* __restrict__ b2o, const float* __restrict__ gamma,
        const float* __restrict__ beta) {
    int s = blockIdx.x, t = threadIdx.x;
    __shared__ float rq[128], rd[128];
    float q = 0.f, d = 0.f;
    if (t < HD) {
        float wt = w2o[s*HD + t];
        float v = 0.f;
        for (int o2 = 0; o2 < HD; ++o2)
            v = fmaf(g_G[t*HD + o2], w2o[s*HD + o2], v);
        q = wt * v;
        d = wt * g_hs[t];
    }
    rq[t] = q; rd[t] = d;
    __syncthreads();
    for (int st = 64; st > 0; st >>= 1) {
        if (t < st) { rq[t] += rq[t+st]; rd[t] += rd[t+st]; }
        __syncthreads();
    }
    if (t == 0) {
        const float N = (float)(BB*CH);
        float bias = b2o[s];
        float dot = rd[0];
        float mu = dot / N + bias;
        float esq = rq[0]/N + 2.f*bias*dot/N + bias*bias;
        float var = esq - mu*mu;
        float a = rsqrtf(var + 1e-5f) * gamma[s];
        g_a  [s] = 0.25f * a;
        g_bsh[s] = 0.25f * (beta[s] + a*(bias - mu));
    }
}

// ---------------- K7f: O = W2o.H2 (tf32) + BN + scatter + relu ----------------
// N=64 channels/block (grid 1024), 128 threads / 4 warps.
// B (H2 chunk) staged once, tf32-rounded. A (w2o) staged per 96-s-row pass,
// tf32-rounded; pass region aliased as Os for the scatter epilogue.
// Warp (mg=w>>1, ng=w&1): 3 m-tiles x n32 -> acc[3][2].
__global__ __launch_bounds__(128) void k7f(const float* __restrict__ w2o,
        const float* __restrict__ x, float* __restrict__ out) {
    __shared__ __align__(16) float Bs[HD*68];     // [k=o][n=c] pitch 68   (19.1KB)
    __shared__ __align__(16) float AsOs[96*76];   // As [sl][o] p76 / Os [c][sl] p100 alias
    float* As = AsOs;
    float* Os = AsOs;
    int tid = threadIdx.x, w = tid >> 5;
    int mg = w >> 1, ng = w & 1;
    int n0 = blockIdx.x << 6;
    int b = n0 >> 10, c0 = n0 & 1023;

    // stage B once (tf32-rounded)
    for (int idx = tid; idx < HD*64; idx += 128) {
        int o = idx >> 6, c = idx & 63;
        Bs[o*68 + c] = tf32r(g_H2[(size_t)(b*HD + o)*CH + c0 + c]);
    }

    int chunk = b >> 4, bt = b & 15;
    int ty = (chunk >> 1)*SP, tx = (chunk & 1)*SP;
    const float* xb = x   + (size_t)(bt*CH + c0)*2304 + ty*48 + tx;
    float*       ob = out + (size_t)(bt*CH + c0)*2304 + ty*48 + tx;

    for (int p = 0; p < 6; ++p) {
        __syncthreads();   // Os region free / Bs ready (p==0)
        // stage A: w2o rows [96p, 96p+96), 18 float4 per row, tf32-rounded
        for (int idx = tid; idx < 96*18; idx += 128) {
            int sl = idx / 18, o4 = (idx - sl*18) * 4;
            float4 v = *(const float4*)(w2o + (size_t)(p*96 + sl)*HD + o4);
            v.x = tf32r(v.x); v.y = tf32r(v.y); v.z = tf32r(v.z); v.w = tf32r(v.w);
            *(float4*)&As[sl*76 + o4] = v;
        }
        __syncthreads();

        wmma::fragment<wmma::accumulator,16,16,8,float> acc[3][2];
#pragma unroll
        for (int i = 0; i < 3; i++)
#pragma unroll
            for (int cf = 0; cf < 2; cf++) wmma::fill_fragment(acc[i][cf], 0.f);

#pragma unroll
        for (int k8 = 0; k8 < 9; ++k8) {
            wmma::fragment<wmma::matrix_b,16,16,8,wmma::precision::tf32,wmma::row_major> bf[2];
            wmma::load_matrix_sync(bf[0], Bs + (k8*8)*68 + ng*32,      68);
            wmma::load_matrix_sync(bf[1], Bs + (k8*8)*68 + ng*32 + 16, 68);
#pragma unroll
            for (int i = 0; i < 3; ++i) {
                wmma::fragment<wmma::matrix_a,16,16,8,wmma::precision::tf32,wmma::row_major> af;
                wmma::load_matrix_sync(af, As + ((mg*3 + i)*16)*76 + k8*8, 76);
                wmma::mma_sync(acc[i][0], af, bf[0], acc[i][0]);
                wmma::mma_sync(acc[i][1], af, bf[1], acc[i][1]);
            }
        }
        __syncthreads();   // all As reads done before Os overwrite
#pragma unroll
        for (int i = 0; i < 3; ++i)
#pragma unroll
            for (int cf = 0; cf < 2; ++cf)
                wmma::store_matrix_sync(Os + (ng*32 + cf*16)*100 + (mg*3 + i)*16,
                                        acc[i][cf], 100, wmma::mem_col_major);
        __syncthreads();
        // scatter: 96 s-rows (sy = 4p+syl) x 64 channels, float4 over sx
        for (int idx = tid; idx < 64*24; idx += 128) {
            int sx4 = idx % 6;
            int t2  = idx / 6;
            int syl = t2 & 3;
            int c   = t2 >> 2;
            int sl  = syl*24 + sx4*4;
            int s0  = p*96 + sl;
            float4 v  = *(float4*)&Os[c*100 + sl];
            float4 av = *(const float4*)&g_a[s0];
            float4 bv = *(const float4*)&g_bsh[s0];
            size_t ga = (size_t)c*2304 + (p*4 + syl)*48 + sx4*4;
            float4 xv = *(const float4*)(xb + ga);
            float4 r;
            r.x = fmaxf(xv.x + fmaf(v.x, av.x, bv.x), 0.f);
            r.y = fmaxf(xv.y + fmaf(v.y, av.y, bv.y), 0.f);
            r.z = fmaxf(xv.z + fmaf(v.z, av.z, bv.z), 0.f);
            r.w = fmaxf(xv.w + fmaf(v.w, av.w, bv.w), 0.f);
            *(float4*)(ob + ga) = r;
        }
    }
}

// ---------------- launch ----------------
extern "C" void kernel_launch(void* const* d_in, const int* in_sizes, int n_in,
                              void* d_out, int out_size) {
    (void)in_sizes; (void)n_in; (void)out_size;
    const float* x      = (const float*)d_in[0];
    const float* w_in1  = (const float*)d_in[1];
    const float* b_in1  = (const float*)d_in[2];
    const float* w_in2  = (const float*)d_in[3];
    const float* b_in2  = (const float*)d_in[4];
    const float* w_out1 = (const float*)d_in[5];
    const float* b_out1 = (const float*)d_in[6];
    const float* w_out2 = (const float*)d_in[7];
    const float* b_out2 = (const float*)d_in[8];
    const float* gamma  = (const float*)d_in[9];
    const float* beta   = (const float*)d_in[10];
    float* out = (float*)d_out;

    kz <<<1, 512>>>();                                   // 1
    kp2<<<1, 640>>>(w_in2, b_in2);                       // 2
    kp1<<<HD, HD>>>(w_out1, w_in2, b_in2);               // 3
    k1_mma<<<(BB*CH)/128, 128>>>(x, w_in1, b_in1);       // 4  <- profiled slot
    k34<<<BB*2, 896>>>();                                // 5
    k56<<<dim3(CH/128, BB), 128>>>(b_out1);              // 6
    k6g<<<BB*2, 288>>>();                                // 7
    k8b<<<SS, 128>>>(w_out2, b_out2, gamma, beta);       // 8
    k7f<<<(BB*CH)/64, 128>>>(w_out2, x, out);            // 9
}

// round 8
// speedup vs baseline: 1.3714x; 1.3077x over previous
#include <cuda_runtime.h>
#include <cuda_bf16.h>
#include <mma.h>
#include <math.h>
#include <cstdint>

using namespace nvcuda;

// Problem constants
#define BT   16
#define CH   1024
#define HW   48
#define SP   24
#define SS   576
#define HD   72
#define BB   64
#define BLK  512
#define KTAY 12
#define JJ   24

// ---------------- scratch ----------------
__device__ __align__(16) float g_H [BB*HD*CH];
__device__ __align__(16) float g_H2[BB*HD*CH];
__device__ __align__(16) float g_xm[BB*CH];
__device__ __align__(16) float g_u [BB*CH];
__device__ __align__(16) float g_t [BB*JJ];
__device__ __align__(16) float g_T [BB*HD*JJ];
__device__ __align__(16) float g_R [BB*HD*JJ];
__device__ __align__(16) float g_M2[HD*HD];
__device__ __align__(16) float g_wv[HD];
__device__ __align__(16) float g_mw2[HD];
__device__ float g_mb2;
__device__ __align__(16) float g_G [HD*HD];
__device__ __align__(16) float g_hs[HD];
__device__ __align__(16) float g_a [SS];
__device__ __align__(16) float g_bsh[SS];

__device__ __forceinline__ float tf32r(float v) { return wmma::__float_to_tf32(v); }

__device__ __forceinline__ void cp_async16(float* smem_dst, const float* gmem_src) {
    unsigned int sa = (unsigned int)__cvta_generic_to_shared(smem_dst);
    asm volatile("cp.async.ca.shared.global [%0], [%1], 16;" :: "r"(sa), "l"(gmem_src));
}

// ---------------- kz ----------------
__global__ void kz() {
    int t = threadIdx.x;
    for (int i = t; i < HD*HD; i += 512) g_G[i] = 0.f;
    if (t < HD) g_hs[t] = 0.f;
}

// ---------------- kp2 ----------------
__global__ void kp2(const float* __restrict__ w2i, const float* __restrict__ b2i) {
    int t = threadIdx.x;
    if (t < HD) {
        float a = 0.f;
        for (int s = 0; s < SS; s++) a += w2i[s*HD + t];
        g_mw2[t] = a * (1.f/SS);
    }
    if (t == 600) {
        float a = 0.f;
        for (int s = 0; s < SS; s++) a += b2i[s];
        g_mb2 = a * (1.f/SS);
    }
}

// ---------------- kp1 ----------------
__global__ void kp1(const float* __restrict__ w1o, const float* __restrict__ w2i,
                    const float* __restrict__ b2i) {
    int o = blockIdx.x, o2 = threadIdx.x;
    float acc = 0.f;
    for (int s = 0; s < SS; s++) acc = fmaf(w1o[o*SS + s], w2i[s*HD + o2], acc);
    g_M2[o*HD + o2] = acc;
    if (o2 == 0) {
        float a2 = 0.f;
        for (int s = 0; s < SS; s++) a2 = fmaf(w1o[o*SS + s], b2i[s], a2);
        g_wv[o] = a2;
    }
}

// ---------------- K1: H = relu(W1.Xg+b1), tf32 wmma + cp.async double buffer ----------------
// 256 threads / 8 warps; warp w owns n16 block w. K=576 in 12 chunks of 48.
__global__ __launch_bounds__(256, 3) void k1_mma(const float* __restrict__ x,
        const float* __restrict__ w1, const float* __restrict__ b1) {
    __shared__ __align__(16) float sm[17472];   // As 80*52 | Bs0 128*52 | Bs1 128*52
    float* As = sm;
    float* Cs = sm;                             // [80][136] alias after loop
    int tid = threadIdx.x, w = tid >> 5;
    int n0 = blockIdx.x << 7;
    int b = n0 >> 10, c0 = n0 & 1023;
    int chunk = b >> 4, bt = b & 15;
    int ty = (chunk >> 1) * SP, tx = (chunk & 1) * SP;
    const float* xb = x + (size_t)(bt*CH + c0) * 2304 + ty*48 + tx;

    wmma::fragment<wmma::accumulator,16,16,8,float> acc[5];
#pragma unroll
    for (int i = 0; i < 5; i++) wmma::fill_fragment(acc[i], 0.f);

    // prefetch B chunk 0
    {
        float* Bn = sm + 4160;
        for (int q = tid; q < 1536; q += 256) {
            int c = q/12, qs = q - c*12;
            int row = (qs >= 6) ? 1 : 0, sxx = (qs - row*6) * 4;
            cp_async16(&Bn[c*52 + row*24 + sxx], xb + (size_t)c*2304 + row*48 + sxx);
        }
        asm volatile("cp.async.commit_group;");
    }

    for (int kc = 0; kc < 12; ++kc) {
        float* Bs = (kc & 1) ? sm + 10816 : sm + 4160;
        asm volatile("cp.async.wait_group 0;");
        __syncthreads();                    // B(kc) visible; prev mma reads done
        if (kc < 11) {                      // prefetch B(kc+1)
            float* Bn = (kc & 1) ? sm + 4160 : sm + 10816;
            int sy0 = (kc + 1) * 2;
            for (int q = tid; q < 1536; q += 256) {
                int c = q/12, qs = q - c*12;
                int row = (qs >= 6) ? 1 : 0, sxx = (qs - row*6) * 4;
                cp_async16(&Bn[c*52 + row*24 + sxx],
                           xb + (size_t)c*2304 + (sy0 + row)*48 + sxx);
            }
            asm volatile("cp.async.commit_group;");
        }
        {   // stage A(kc), tf32 RN rounded
            int k0 = kc * 48;
            for (int idx = tid; idx < 960; idx += 256) {
                int o = idx/12, k4 = (idx - o*12) * 4;
                float4 v = make_float4(0.f, 0.f, 0.f, 0.f);
                if (o < HD) {
                    v = *(const float4*)(w1 + o*SS + k0 + k4);
                    v.x = tf32r(v.x); v.y = tf32r(v.y); v.z = tf32r(v.z); v.w = tf32r(v.w);
                }
                *(float4*)&As[o*52 + k4] = v;
            }
        }
        // round B(kc) in place (RN)
        for (int q = tid; q < 1536; q += 256) {
            int c = q/12, qs = q - c*12;
            int row = (qs >= 6) ? 1 : 0, sxx = (qs - row*6) * 4;
            float4* p = (float4*)&Bs[c*52 + row*24 + sxx];
            float4 v = *p;
            v.x = tf32r(v.x); v.y = tf32r(v.y); v.z = tf32r(v.z); v.w = tf32r(v.w);
            *p = v;
        }
        __syncthreads();
#pragma unroll
        for (int k8 = 0; k8 < 6; ++k8) {
            wmma::fragment<wmma::matrix_b,16,16,8,wmma::precision::tf32,wmma::col_major> bf;
            wmma::load_matrix_sync(bf, Bs + (w*16)*52 + k8*8, 52);
#pragma unroll
            for (int i = 0; i < 5; ++i) {
                wmma::fragment<wmma::matrix_a,16,16,8,wmma::precision::tf32,wmma::row_major> af;
                wmma::load_matrix_sync(af, As + (i*16)*52 + k8*8, 52);
                wmma::mma_sync(acc[i], af, bf, acc[i]);
            }
        }
    }
    __syncthreads();
#pragma unroll
    for (int i = 0; i < 5; ++i)
        wmma::store_matrix_sync(Cs + (i*16)*136 + w*16, acc[i], 136, wmma::mem_row_major);
    __syncthreads();
    for (int idx = tid; idx < 2304; idx += 256) {
        int o = idx >> 5, cq = (idx & 31) << 2;
        float bias = __ldg(&b1[o]);
        float4 v = *(float4*)&Cs[o*136 + cq];
        v.x = fmaxf(v.x + bias, 0.f); v.y = fmaxf(v.y + bias, 0.f);
        v.z = fmaxf(v.z + bias, 0.f); v.w = fmaxf(v.w + bias, 0.f);
        *(float4*)&g_H[(size_t)(b*HD + o)*CH + c0 + cq] = v;
    }
    if (tid < 128) {
        int c = tid;
        float a = g_mb2;
#pragma unroll 8
        for (int o = 0; o < HD; o++) {
            float h = fmaxf(Cs[o*136 + c] + __ldg(&b1[o]), 0.f);
            a = fmaf(g_mw2[o], h, a);
        }
        g_xm[b*CH + c0 + c] = a;
        g_u [b*CH + c0 + c] = expf(-a*a);
    }
}

// ---------------- K34: T (and moments t as ones-row) ----------------
__global__ __launch_bounds__(896) void k34() {
    int bb = blockIdx.x; int b = bb >> 1, blk = bb & 1;
    int tid = threadIdx.x;
    int o = tid / KTAY, k = tid - o*KTAY;   // valid for tid < 876
    __shared__ float Hs[73][65];
    __shared__ float ws[KTAY][66];
    float acc = 0.f;
    for (int c0 = 0; c0 < BLK; c0 += 64) {
        if (tid < KTAY*64) {
            int kk = tid >> 6, cc = tid & 63;
            int c = b*CH + blk*BLK + c0 + cc;
            float xm = g_xm[c], pw = g_u[c];
            for (int t = 0; t < kk; t++) pw *= xm;
            ws[kk][cc] = pw;
        }
        for (int idx = tid; idx < 73*64; idx += 896) {
            int o2 = idx >> 6, cc = idx & 63;
            Hs[o2][cc] = (o2 < HD) ? g_H[(size_t)(b*HD + o2)*CH + blk*BLK + c0 + cc] : 1.f;
        }
        __syncthreads();
        if (tid < 876) {
#pragma unroll
            for (int cc = 0; cc < 64; cc++) acc = fmaf(Hs[o][cc], ws[k][cc], acc);
        }
        __syncthreads();
    }
    if (tid < 876) {
        if (o < HD) g_T[(b*HD + o)*JJ + blk*KTAY + k] = acc;
        else        g_t[bb*KTAY + k] = acc;
    }
}

// ---------------- K5: R = M2.T + wv (x) t  (once per b) ----------------
__global__ __launch_bounds__(288) void k5_R() {
    int b = blockIdx.x, tid = threadIdx.x;
    __shared__ float Ts[HD*JJ];
    __shared__ float tb[JJ];
    for (int idx = tid; idx < HD*JJ; idx += 288) Ts[idx] = g_T[b*HD*JJ + idx];
    if (tid < JJ) tb[tid] = g_t[b*JJ + tid];
    __syncthreads();
    for (int idx = tid; idx < HD*JJ; idx += 288) {
        int o = idx / JJ, jj = idx - o*JJ;
        float acc = g_wv[o] * tb[jj];
#pragma unroll 8
        for (int o2 = 0; o2 < HD; o2++)
            acc = fmaf(g_M2[o*HD + o2], Ts[o2*JJ + jj], acc);
        g_R[b*HD*JJ + idx] = acc;
    }
}

// ---------------- K6: H2 from R ----------------
__global__ __launch_bounds__(512) void k6_H2(const float* __restrict__ b1o) {
    int b = blockIdx.y;
    int d = blockIdx.x * 512 + threadIdx.x;
    int blk = d >> 9;
    int tid = threadIdx.x;
    __shared__ float Rs[HD*JJ];
    __shared__ float tb[JJ];
    __shared__ float bo[HD];
    for (int idx = tid; idx < HD*JJ; idx += 512) Rs[idx] = g_R[b*HD*JJ + idx];
    if (tid < JJ) tb[tid] = g_t[b*JJ + tid];
    if (tid < HD) bo[tid] = b1o[tid];
    __syncthreads();
    float xm = g_xm[b*CH + d];
    float p[KTAY];
    p[0] = 1.f;
#pragma unroll
    for (int k = 1; k < KTAY; k++) p[k] = p[k-1] * (2.f * xm / (float)k);
    float denom = 0.f;
#pragma unroll
    for (int k = 0; k < KTAY; k++) denom = fmaf(p[k], tb[blk*KTAY + k], denom);
    float inv = 1.0f / denom;
    for (int o = 0; o < HD; o++) {
        float acc = 0.f;
#pragma unroll
        for (int k = 0; k < KTAY; k++) acc = fmaf(Rs[o*JJ + blk*KTAY + k], p[k], acc);
        g_H2[(size_t)(b*HD + o)*CH + d] = fmaxf(fmaf(acc, inv, bo[o]), 0.f);
    }
}

// ---------------- K6g: Gram ----------------
__global__ __launch_bounds__(288) void k6g() {
    int blk = blockIdx.x;
    int b = blk >> 1, c0 = (blk & 1) << 9;
    int tid = threadIdx.x;
    int i0 = (tid % 24) * 3, j0 = (tid / 24) * 6;
    __shared__ float Hs[HD][65];
    float acc[3][6];
#pragma unroll
    for (int i = 0; i < 3; i++)
#pragma unroll
        for (int j = 0; j < 6; j++) acc[i][j] = 0.f;
    float hs = 0.f;
    for (int cc0 = 0; cc0 < 512; cc0 += 64) {
        for (int idx = tid; idx < HD*64; idx += 288) {
            int o = idx >> 6, cc = idx & 63;
            Hs[o][cc] = g_H2[(size_t)(b*HD + o)*CH + c0 + cc0 + cc];
        }
        __syncthreads();
        if (tid < HD) {
#pragma unroll 16
            for (int cc = 0; cc < 64; cc++) hs += Hs[tid][cc];
        }
#pragma unroll 4
        for (int cc = 0; cc < 64; cc++) {
            float a0 = Hs[i0][cc], a1 = Hs[i0+1][cc], a2 = Hs[i0+2][cc];
#pragma unroll
            for (int jj = 0; jj < 6; ++jj) {
                float bv = Hs[j0+jj][cc];
                acc[0][jj] = fmaf(a0, bv, acc[0][jj]);
                acc[1][jj] = fmaf(a1, bv, acc[1][jj]);
                acc[2][jj] = fmaf(a2, bv, acc[2][jj]);
            }
        }
        __syncthreads();
    }
#pragma unroll
    for (int ii = 0; ii < 3; ii++)
#pragma unroll
        for (int jj = 0; jj < 6; jj++)
            atomicAdd(&g_G[(i0+ii)*HD + j0+jj], acc[ii][jj]);
    if (tid < HD) atomicAdd(&g_hs[tid], hs);
}

// ---------------- K8b: analytic BN stats ----------------
__global__ __launch_bounds__(128) void k8b(const float* __restrict__ w2o,
        const float* __restrict__ b2o, const float* __restrict__ gamma,
        const float* __restrict__ beta) {
    int s = blockIdx.x, t = threadIdx.x;
    __shared__ float rq[128], rd[128];
    float q = 0.f, d = 0.f;
    if (t < HD) {
        float wt = w2o[s*HD + t];
        float v = 0.f;
        for (int o2 = 0; o2 < HD; ++o2)
            v = fmaf(g_G[t*HD + o2], w2o[s*HD + o2], v);
        q = wt * v;
        d = wt * g_hs[t];
    }
    rq[t] = q; rd[t] = d;
    __syncthreads();
    for (int st = 64; st > 0; st >>= 1) {
        if (t < st) { rq[t] += rq[t+st]; rd[t] += rd[t+st]; }
        __syncthreads();
    }
    if (t == 0) {
        const float N = (float)(BB*CH);
        float bias = b2o[s];
        float dot = rd[0];
        float mu = dot / N + bias;
        float esq = rq[0]/N + 2.f*bias*dot/N + bias*bias;
        float var = esq - mu*mu;
        float a = rsqrtf(var + 1e-5f) * gamma[s];
        g_a  [s] = 0.25f * a;
        g_bsh[s] = 0.25f * (beta[s] + a*(bias - mu));
    }
}

// ---------------- K7f: O = W2o.H2 (tf32) + BN + scatter + relu, 12 warps ----------------
// N=64 channels/block (grid 1024), 384 threads. Warp w: mg=w>>1 (m16 tile in 96-row pass),
// ng=w&1 (n32). B (H2) staged once; A (w2o) per pass; pass region aliased as Os.
__global__ __launch_bounds__(384, 3) void k7f(const float* __restrict__ w2o,
        const float* __restrict__ x, float* __restrict__ out) {
    __shared__ __align__(16) float Bs[HD*68];     // [o][c] pitch 68
    __shared__ __align__(16) float AsOs[7296];    // As [sl][o] p76  /  Os [c][sl] p100
    float* As = AsOs;
    float* Os = AsOs;
    int tid = threadIdx.x, w = tid >> 5;
    int mg = w >> 1, ng = w & 1;
    int n0 = blockIdx.x << 6;
    int b = n0 >> 10, c0 = n0 & 1023;

    for (int idx = tid; idx < HD*64; idx += 384) {
        int o = idx >> 6, c = idx & 63;
        Bs[o*68 + c] = tf32r(g_H2[(size_t)(b*HD + o)*CH + c0 + c]);
    }

    int chunk = b >> 4, bt = b & 15;
    int ty = (chunk >> 1)*SP, tx = (chunk & 1)*SP;
    const float* xb = x   + (size_t)(bt*CH + c0)*2304 + ty*48 + tx;
    float*       ob = out + (size_t)(bt*CH + c0)*2304 + ty*48 + tx;

    for (int p = 0; p < 6; ++p) {
        __syncthreads();   // Bs ready (p=0) / Os reads done (p>0)
        for (int idx = tid; idx < 1728; idx += 384) {
            int sl = idx / 18, o4 = (idx - sl*18) * 4;
            float4 v = *(const float4*)(w2o + (size_t)(p*96 + sl)*HD + o4);
            v.x = tf32r(v.x); v.y = tf32r(v.y); v.z = tf32r(v.z); v.w = tf32r(v.w);
            *(float4*)&As[sl*76 + o4] = v;
        }
        __syncthreads();

        wmma::fragment<wmma::accumulator,16,16,8,float> acc[2];
        wmma::fill_fragment(acc[0], 0.f);
        wmma::fill_fragment(acc[1], 0.f);
#pragma unroll
        for (int k8 = 0; k8 < 9; ++k8) {
            wmma::fragment<wmma::matrix_b,16,16,8,wmma::precision::tf32,wmma::row_major> bf[2];
            wmma::load_matrix_sync(bf[0], Bs + (k8*8)*68 + ng*32,      68);
            wmma::load_matrix_sync(bf[1], Bs + (k8*8)*68 + ng*32 + 16, 68);
            wmma::fragment<wmma::matrix_a,16,16,8,wmma::precision::tf32,wmma::row_major> af;
            wmma::load_matrix_sync(af, As + (mg*16)*76 + k8*8, 76);
            wmma::mma_sync(acc[0], af, bf[0], acc[0]);
            wmma::mma_sync(acc[1], af, bf[1], acc[1]);
        }
        __syncthreads();   // all As reads done before Os overwrite
#pragma unroll
        for (int cf = 0; cf < 2; ++cf)
            wmma::store_matrix_sync(Os + (ng*32 + cf*16)*100 + mg*16,
                                    acc[cf], 100, wmma::mem_col_major);
        __syncthreads();
        for (int idx = tid; idx < 1536; idx += 384) {
            int sx4 = idx % 6;
            int t2  = idx / 6;
            int syl = t2 & 3;
            int c   = t2 >> 2;
            int sl  = syl*24 + sx4*4;
            int s0  = p*96 + sl;
            float4 v  = *(float4*)&Os[c*100 + sl];
            float4 av = *(const float4*)&g_a[s0];
            float4 bv = *(const float4*)&g_bsh[s0];
            size_t ga = (size_t)c*2304 + (p*4 + syl)*48 + sx4*4;
            float4 xv = *(const float4*)(xb + ga);
            float4 r;
            r.x = fmaxf(xv.x + fmaf(v.x, av.x, bv.x), 0.f);
            r.y = fmaxf(xv.y + fmaf(v.y, av.y, bv.y), 0.f);
            r.z = fmaxf(xv.z + fmaf(v.z, av.z, bv.z), 0.f);
            r.w = fmaxf(xv.w + fmaf(v.w, av.w, bv.w), 0.f);
            *(float4*)(ob + ga) = r;
        }
    }
}

// ---------------- launch ----------------
extern "C" void kernel_launch(void* const* d_in, const int* in_sizes, int n_in,
                              void* d_out, int out_size) {
    (void)in_sizes; (void)n_in; (void)out_size;
    const float* x      = (const float*)d_in[0];
    const float* w_in1  = (const float*)d_in[1];
    const float* b_in1  = (const float*)d_in[2];
    const float* w_in2  = (const float*)d_in[3];
    const float* b_in2  = (const float*)d_in[4];
    const float* w_out1 = (const float*)d_in[5];
    const float* b_out1 = (const float*)d_in[6];
    const float* w_out2 = (const float*)d_in[7];
    const float* b_out2 = (const float*)d_in[8];
    const float* gamma  = (const float*)d_in[9];
    const float* beta   = (const float*)d_in[10];
    float* out = (float*)d_out;

    kz <<<1, 512>>>();                                   // 1
    kp2<<<1, 640>>>(w_in2, b_in2);                       // 2
    kp1<<<HD, HD>>>(w_out1, w_in2, b_in2);               // 3
    k1_mma<<<(BB*CH)/128, 256>>>(x, w_in1, b_in1);       // 4  <- profiled slot
    k34<<<BB*2, 896>>>();                                // 5
    k5_R<<<BB, 288>>>();                                 // 6
    k6_H2<<<dim3(CH/512, BB), 512>>>(b_out1);            // 7
    k6g<<<BB*2, 288>>>();                                // 8
    k8b<<<SS, 128>>>(w_out2, b_out2, gamma, beta);       // 9
    k7f<<<(BB*CH)/64, 384>>>(w_out2, x, out);            // 10
}

// round 10
// speedup vs baseline: 1.4455x; 1.0540x over previous
#include <cuda_runtime.h>
#include <cuda_bf16.h>
#include <mma.h>
#include <math.h>
#include <cstdint>

using namespace nvcuda;

// Problem constants
#define BT   16
#define CH   1024
#define HW   48
#define SP   24
#define SS   576
#define HD   72
#define BB   64
#define BLK  512
#define KTAY 12
#define JJ   24

// ---------------- scratch ----------------
__device__ __align__(16) float g_H2[BB*HD*CH];      // tf32-rounded H2
__device__ __align__(16) float g_xm[BB*CH];
__device__ __align__(16) float g_u [BB*CH];
__device__ __align__(16) float g_t [BB*JJ];         // atomically accumulated
__device__ __align__(16) float g_T [BB*HD*JJ];      // atomically accumulated
__device__ __align__(16) float g_R [BB*HD*JJ];
__device__ __align__(16) float g_M2[HD*HD];
__device__ __align__(16) float g_wv[HD];
__device__ __align__(16) float g_mw2[HD];
__device__ float g_mb2;
__device__ __align__(16) float g_G [HD*HD];
__device__ __align__(16) float g_hs[HD];
__device__ __align__(16) float g_a [SS];
__device__ __align__(16) float g_bsh[SS];
__device__ __align__(16) float g_W1r[80*SS];        // tf32-rounded w_in1, rows 72..79 = 0
__device__ __align__(16) float g_W2r[SS*HD];        // tf32-rounded w_out2

__device__ __forceinline__ float tf32r(float v) { return wmma::__float_to_tf32(v); }

__device__ __forceinline__ void cp_async16(float* smem_dst, const float* gmem_src) {
    unsigned int sa = (unsigned int)__cvta_generic_to_shared(smem_dst);
    asm volatile("cp.async.ca.shared.global [%0], [%1], 16;" :: "r"(sa), "l"(gmem_src));
}

// ---------------- kz: zero accumulators ----------------
__global__ void kz() {
    int i0 = blockIdx.x*512 + threadIdx.x, stride = gridDim.x*512;
    for (int i = i0; i < BB*HD*JJ; i += stride) g_T[i] = 0.f;
    for (int i = i0; i < BB*JJ;    i += stride) g_t[i] = 0.f;
    for (int i = i0; i < HD*HD;    i += stride) g_G[i] = 0.f;
    for (int i = i0; i < HD;       i += stride) g_hs[i] = 0.f;
}

// ---------------- kpr: pre-round weights to tf32 (RN) ----------------
__global__ void kpr(const float* __restrict__ w1, const float* __restrict__ w2o) {
    int i0 = blockIdx.x*512 + threadIdx.x, stride = gridDim.x*512;
    for (int idx = i0; idx < 80*SS; idx += stride) {
        int o = idx / SS;
        g_W1r[idx] = (o < HD) ? tf32r(w1[idx]) : 0.f;
    }
    for (int idx = i0; idx < SS*HD; idx += stride)
        g_W2r[idx] = tf32r(w2o[idx]);
}

// ---------------- kp2 ----------------
__global__ void kp2(const float* __restrict__ w2i, const float* __restrict__ b2i) {
    int t = threadIdx.x;
    if (t < HD) {
        float a = 0.f;
        for (int s = 0; s < SS; s++) a += w2i[s*HD + t];
        g_mw2[t] = a * (1.f/SS);
    }
    if (t == 600) {
        float a = 0.f;
        for (int s = 0; s < SS; s++) a += b2i[s];
        g_mb2 = a * (1.f/SS);
    }
}

// ---------------- kp1 ----------------
__global__ void kp1(const float* __restrict__ w1o, const float* __restrict__ w2i,
                    const float* __restrict__ b2i) {
    int o = blockIdx.x, o2 = threadIdx.x;
    float acc = 0.f;
    for (int s = 0; s < SS; s++) acc = fmaf(w1o[o*SS + s], w2i[s*HD + o2], acc);
    g_M2[o*HD + o2] = acc;
    if (o2 == 0) {
        float a2 = 0.f;
        for (int s = 0; s < SS; s++) a2 = fmaf(w1o[o*SS + s], b2i[s], a2);
        g_wv[o] = a2;
    }
}

// ---------------- K1: H=relu(W1.Xg+b1) tf32 wmma, cp.async A+B, fused xm + T ----------------
// 256 threads / 8 warps; warp w owns n16 block w. K=576 in 12 chunks of 48.
// Epilogue: xm/u, then partial T/t atomically (g_H never materialized).
__global__ __launch_bounds__(256, 3) void k1_mma(const float* __restrict__ x,
        const float* __restrict__ b1) {
    __shared__ __align__(16) float sm[17472];   // As 80*52 | Bs0 128*52 | Bs1 128*52
    float* As = sm;
    float* Cs = sm;                             // [80][136] alias after loop
    float* xs = sm + 10880;                     // [128]
    float* us = sm + 11008;                     // [128]
    float* ws = sm + 11136;                     // [12][128]
    int tid = threadIdx.x, w = tid >> 5;
    int n0 = blockIdx.x << 7;
    int b = n0 >> 10, c0 = n0 & 1023;
    int chunk = b >> 4, bt = b & 15;
    int ty = (chunk >> 1) * SP, tx = (chunk & 1) * SP;
    const float* xb = x + (size_t)(bt*CH + c0) * 2304 + ty*48 + tx;

    wmma::fragment<wmma::accumulator,16,16,8,float> acc[5];
#pragma unroll
    for (int i = 0; i < 5; i++) wmma::fill_fragment(acc[i], 0.f);

    // prefetch B chunk 0
    {
        float* Bn = sm + 4160;
        for (int q = tid; q < 1536; q += 256) {
            int c = q/12, qs = q - c*12;
            int row = (qs >= 6) ? 1 : 0, sxx = (qs - row*6) * 4;
            cp_async16(&Bn[c*52 + row*24 + sxx], xb + (size_t)c*2304 + row*48 + sxx);
        }
        asm volatile("cp.async.commit_group;");
    }

    for (int kc = 0; kc < 12; ++kc) {
        float* Bs = (kc & 1) ? sm + 10816 : sm + 4160;
        __syncthreads();                 // prior mma done reading As / Bn region
        // stage A(kc) via cp.async (pre-rounded, L2-hot)
        for (int q = tid; q < 960; q += 256) {
            int o = q/12, k4 = (q - o*12) * 4;
            cp_async16(&As[o*52 + k4], g_W1r + o*SS + kc*48 + k4);
        }
        asm volatile("cp.async.commit_group;");
        if (kc < 11) {                   // prefetch B(kc+1)
            float* Bn = (kc & 1) ? sm + 4160 : sm + 10816;
            int sy0 = (kc + 1) * 2;
            for (int q = tid; q < 1536; q += 256) {
                int c = q/12, qs = q - c*12;
                int row = (qs >= 6) ? 1 : 0, sxx = (qs - row*6) * 4;
                cp_async16(&Bn[c*52 + row*24 + sxx],
                           xb + (size_t)c*2304 + (sy0 + row)*48 + sxx);
            }
            asm volatile("cp.async.commit_group;");
            asm volatile("cp.async.wait_group 1;");   // B(kc)+A(kc) done, B(kc+1) in flight
        } else {
            asm volatile("cp.async.wait_group 0;");
        }
        __syncthreads();
#pragma unroll
        for (int k8 = 0; k8 < 6; ++k8) {
            wmma::fragment<wmma::matrix_b,16,16,8,wmma::precision::tf32,wmma::col_major> bf;
            wmma::load_matrix_sync(bf, Bs + (w*16)*52 + k8*8, 52);
#pragma unroll
            for (int e = 0; e < 4; e++) bf.x[e] = tf32r(bf.x[e]);
#pragma unroll
            for (int i = 0; i < 5; ++i) {
                wmma::fragment<wmma::matrix_a,16,16,8,wmma::precision::tf32,wmma::row_major> af;
                wmma::load_matrix_sync(af, As + (i*16)*52 + k8*8, 52);
                wmma::mma_sync(acc[i], af, bf, acc[i]);
            }
        }
    }
    __syncthreads();
#pragma unroll
    for (int i = 0; i < 5; ++i)
        wmma::store_matrix_sync(Cs + (i*16)*136 + w*16, acc[i], 136, wmma::mem_row_major);
    __syncthreads();
    // xm/u for these 128 channels
    if (tid < 128) {
        int c = tid;
        float a = g_mb2;
#pragma unroll 8
        for (int o = 0; o < HD; o++) {
            float h = fmaxf(Cs[o*136 + c] + __ldg(&b1[o]), 0.f);
            a = fmaf(g_mw2[o], h, a);
        }
        g_xm[b*CH + c0 + c] = a;
        float uu = expf(-a*a);
        g_u [b*CH + c0 + c] = uu;
        xs[c] = a; us[c] = uu;
    }
    __syncthreads();
    // ws[k][c] = u * xm^k
    for (int q = tid; q < KTAY*128; q += 256) {
        int k = q >> 7, c = q & 127;
        float pw = us[c], xv = xs[c];
        for (int t = 0; t < k; t++) pw *= xv;
        ws[q] = pw;
    }
    __syncthreads();
    // partial T (o<72) and t (o==72, ones row), atomic accumulate
    int blk = (c0 >> 9);
    for (int q = tid; q < 876; q += 256) {
        int o = q / KTAY, k = q - o*KTAY;
        float s = 0.f;
        if (o < HD) {
            float bias = __ldg(&b1[o]);
            const float* cr = Cs + o*136;
            const float* wr = ws + k*128;
#pragma unroll 8
            for (int c = 0; c < 128; c++)
                s = fmaf(fmaxf(cr[c] + bias, 0.f), wr[c], s);
            atomicAdd(&g_T[(b*HD + o)*JJ + blk*KTAY + k], s);
        } else {
            const float* wr = ws + k*128;
#pragma unroll 8
            for (int c = 0; c < 128; c++) s += wr[c];
            atomicAdd(&g_t[(b*2 + blk)*KTAY + k], s);
        }
    }
}

// ---------------- K5: R = M2.T + wv (x) t  (once per b) ----------------
__global__ __launch_bounds__(288) void k5_R() {
    int b = blockIdx.x, tid = threadIdx.x;
    __shared__ float Ts[HD*JJ];
    __shared__ float tb[JJ];
    for (int idx = tid; idx < HD*JJ; idx += 288) Ts[idx] = g_T[b*HD*JJ + idx];
    if (tid < JJ) tb[tid] = g_t[b*JJ + tid];
    __syncthreads();
    for (int idx = tid; idx < HD*JJ; idx += 288) {
        int o = idx / JJ, jj = idx - o*JJ;
        float acc = g_wv[o] * tb[jj];
#pragma unroll 8
        for (int o2 = 0; o2 < HD; o2++)
            acc = fmaf(g_M2[o*HD + o2], Ts[o2*JJ + jj], acc);
        g_R[b*HD*JJ + idx] = acc;
    }
}

// ---------------- K6: H2 from R (written tf32-rounded) ----------------
__global__ __launch_bounds__(512) void k6_H2(const float* __restrict__ b1o) {
    int b = blockIdx.y;
    int d = blockIdx.x * 512 + threadIdx.x;
    int blk = d >> 9;
    int tid = threadIdx.x;
    __shared__ float Rs[HD*JJ];
    __shared__ float tb[JJ];
    __shared__ float bo[HD];
    for (int idx = tid; idx < HD*JJ; idx += 512) Rs[idx] = g_R[b*HD*JJ + idx];
    if (tid < JJ) tb[tid] = g_t[b*JJ + tid];
    if (tid < HD) bo[tid] = b1o[tid];
    __syncthreads();
    float xm = g_xm[b*CH + d];
    float p[KTAY];
    p[0] = 1.f;
#pragma unroll
    for (int k = 1; k < KTAY; k++) p[k] = p[k-1] * (2.f * xm / (float)k);
    float denom = 0.f;
#pragma unroll
    for (int k = 0; k < KTAY; k++) denom = fmaf(p[k], tb[blk*KTAY + k], denom);
    float inv = 1.0f / denom;
    for (int o = 0; o < HD; o++) {
        float acc = 0.f;
#pragma unroll
        for (int k = 0; k < KTAY; k++) acc = fmaf(Rs[o*JJ + blk*KTAY + k], p[k], acc);
        g_H2[(size_t)(b*HD + o)*CH + d] = tf32r(fmaxf(fmaf(acc, inv, bo[o]), 0.f));
    }
}

// ---------------- K6g: Gram (on rounded H2 — matches actual GEMM inputs) ----------------
__global__ __launch_bounds__(288) void k6g() {
    int blk = blockIdx.x;
    int b = blk >> 1, c0 = (blk & 1) << 9;
    int tid = threadIdx.x;
    int i0 = (tid % 24) * 3, j0 = (tid / 24) * 6;
    __shared__ float Hs[HD][65];
    float acc[3][6];
#pragma unroll
    for (int i = 0; i < 3; i++)
#pragma unroll
        for (int j = 0; j < 6; j++) acc[i][j] = 0.f;
    float hs = 0.f;
    for (int cc0 = 0; cc0 < 512; cc0 += 64) {
        for (int idx = tid; idx < HD*64; idx += 288) {
            int o = idx >> 6, cc = idx & 63;
            Hs[o][cc] = g_H2[(size_t)(b*HD + o)*CH + c0 + cc0 + cc];
        }
        __syncthreads();
        if (tid < HD) {
#pragma unroll 16
            for (int cc = 0; cc < 64; cc++) hs += Hs[tid][cc];
        }
#pragma unroll 4
        for (int cc = 0; cc < 64; cc++) {
            float a0 = Hs[i0][cc], a1 = Hs[i0+1][cc], a2 = Hs[i0+2][cc];
#pragma unroll
            for (int jj = 0; jj < 6; ++jj) {
                float bv = Hs[j0+jj][cc];
                acc[0][jj] = fmaf(a0, bv, acc[0][jj]);
                acc[1][jj] = fmaf(a1, bv, acc[1][jj]);
                acc[2][jj] = fmaf(a2, bv, acc[2][jj]);
            }
        }
        __syncthreads();
    }
#pragma unroll
    for (int ii = 0; ii < 3; ii++)
#pragma unroll
        for (int jj = 0; jj < 6; jj++)
            atomicAdd(&g_G[(i0+ii)*HD + j0+jj], acc[ii][jj]);
    if (tid < HD) atomicAdd(&g_hs[tid], hs);
}

// ---------------- K8b: analytic BN stats (rounded w2o for consistency) ----------------
__global__ __launch_bounds__(128) void k8b(const float* __restrict__ b2o,
        const float* __restrict__ gamma, const float* __restrict__ beta) {
    int s = blockIdx.x, t = threadIdx.x;
    __shared__ float rq[128], rd[128];
    float q = 0.f, d = 0.f;
    if (t < HD) {
        float wt = g_W2r[s*HD + t];
        float v = 0.f;
        for (int o2 = 0; o2 < HD; ++o2)
            v = fmaf(g_G[t*HD + o2], g_W2r[s*HD + o2], v);
        q = wt * v;
        d = wt * g_hs[t];
    }
    rq[t] = q; rd[t] = d;
    __syncthreads();
    for (int st = 64; st > 0; st >>= 1) {
        if (t < st) { rq[t] += rq[t+st]; rd[t] += rd[t+st]; }
        __syncthreads();
    }
    if (t == 0) {
        const float N = (float)(BB*CH);
        float bias = b2o[s];
        float dot = rd[0];
        float mu = dot / N + bias;
        float esq = rq[0]/N + 2.f*bias*dot/N + bias*bias;
        float var = esq - mu*mu;
        float a = rsqrtf(var + 1e-5f) * gamma[s];
        g_a  [s] = 0.25f * a;
        g_bsh[s] = 0.25f * (beta[s] + a*(bias - mu));
    }
}

// ---------------- K7f: O = W2r.H2 (tf32) + BN + scatter + relu ----------------
// N=64 channels/block (grid 1024), 384 threads / 12 warps. All inputs pre-rounded;
// staging via cp.async only. Warp: mg=w>>1 (m16 tile), ng=w&1 (n32).
__global__ __launch_bounds__(384, 3) void k7f(const float* __restrict__ x,
        float* __restrict__ out) {
    __shared__ __align__(16) float Bs[HD*68];     // [o][c] pitch 68
    __shared__ __align__(16) float AsOs[7296];    // As [sl][o] p76  /  Os [c][sl] p100
    float* As = AsOs;
    float* Os = AsOs;
    int tid = threadIdx.x, w = tid >> 5;
    int mg = w >> 1, ng = w & 1;
    int n0 = blockIdx.x << 6;
    int b = n0 >> 10, c0 = n0 & 1023;

    // stage B via cp.async (already tf32-rounded)
    for (int q = tid; q < HD*16; q += 384) {
        int o = q >> 4, c4 = (q & 15) * 4;
        cp_async16(&Bs[o*68 + c4], g_H2 + (size_t)(b*HD + o)*CH + c0 + c4);
    }
    asm volatile("cp.async.commit_group;");

    int chunk = b >> 4, bt = b & 15;
    int ty = (chunk >> 1)*SP, tx = (chunk & 1)*SP;
    const float* xb = x   + (size_t)(bt*CH + c0)*2304 + ty*48 + tx;
    float*       ob = out + (size_t)(bt*CH + c0)*2304 + ty*48 + tx;

    for (int p = 0; p < 6; ++p) {
        __syncthreads();   // Os/As free (prev scatter done)
        // stage A rows [96p, 96p+96) via cp.async (pre-rounded w2o)
        for (int q = tid; q < 96*18; q += 384) {
            int sl = q / 18, o4 = (q - sl*18) * 4;
            cp_async16(&As[sl*76 + o4], g_W2r + (size_t)(p*96 + sl)*HD + o4);
        }
        asm volatile("cp.async.commit_group;");
        asm volatile("cp.async.wait_group 0;");
        __syncthreads();

        wmma::fragment<wmma::accumulator,16,16,8,float> acc[2];
        wmma::fill_fragment(acc[0], 0.f);
        wmma::fill_fragment(acc[1], 0.f);
#pragma unroll
        for (int k8 = 0; k8 < 9; ++k8) {
            wmma::fragment<wmma::matrix_b,16,16,8,wmma::precision::tf32,wmma::row_major> bf[2];
            wmma::load_matrix_sync(bf[0], Bs + (k8*8)*68 + ng*32,      68);
            wmma::load_matrix_sync(bf[1], Bs + (k8*8)*68 + ng*32 + 16, 68);
            wmma::fragment<wmma::matrix_a,16,16,8,wmma::precision::tf32,wmma::row_major> af;
            wmma::load_matrix_sync(af, As + (mg*16)*76 + k8*8, 76);
            wmma::mma_sync(acc[0], af, bf[0], acc[0]);
            wmma::mma_sync(acc[1], af, bf[1], acc[1]);
        }
        __syncthreads();   // As reads done before Os overwrite
#pragma unroll
        for (int cf = 0; cf < 2; ++cf)
            wmma::store_matrix_sync(Os + (ng*32 + cf*16)*100 + mg*16,
                                    acc[cf], 100, wmma::mem_col_major);
        __syncthreads();
        for (int idx = tid; idx < 1536; idx += 384) {
            int sx4 = idx % 6;
            int t2  = idx / 6;
            int syl = t2 & 3;
            int c   = t2 >> 2;
            int sl  = syl*24 + sx4*4;
            int s0  = p*96 + sl;
            float4 v  = *(float4*)&Os[c*100 + sl];
            float4 av = *(const float4*)&g_a[s0];
            float4 bv = *(const float4*)&g_bsh[s0];
            size_t ga = (size_t)c*2304 + (p*4 + syl)*48 + sx4*4;
            float4 xv = *(const float4*)(xb + ga);
            float4 r;
            r.x = fmaxf(xv.x + fmaf(v.x, av.x, bv.x), 0.f);
            r.y = fmaxf(xv.y + fmaf(v.y, av.y, bv.y), 0.f);
            r.z = fmaxf(xv.z + fmaf(v.z, av.z, bv.z), 0.f);
            r.w = fmaxf(xv.w + fmaf(v.w, av.w, bv.w), 0.f);
            *(float4*)(ob + ga) = r;
        }
    }
}

// ---------------- launch ----------------
extern "C" void kernel_launch(void* const* d_in, const int* in_sizes, int n_in,
                              void* d_out, int out_size) {
    (void)in_sizes; (void)n_in; (void)out_size;
    const float* x      = (const float*)d_in[0];
    const float* w_in1  = (const float*)d_in[1];
    const float* b_in1  = (const float*)d_in[2];
    const float* w_in2  = (const float*)d_in[3];
    const float* b_in2  = (const float*)d_in[4];
    const float* w_out1 = (const float*)d_in[5];
    const float* b_out1 = (const float*)d_in[6];
    const float* w_out2 = (const float*)d_in[7];
    const float* b_out2 = (const float*)d_in[8];
    const float* gamma  = (const float*)d_in[9];
    const float* beta   = (const float*)d_in[10];
    float* out = (float*)d_out;

    kz <<<64, 512>>>();                                  // 1
    kp2<<<1, 640>>>(w_in2, b_in2);                       // 2
    kpr<<<64, 512>>>(w_in1, w_out2);                     // 3
    k1_mma<<<(BB*CH)/128, 256>>>(x, b_in1);              // 4  <- profiled slot
    kp1<<<HD, HD>>>(w_out1, w_in2, b_in2);               // 5
    k5_R<<<BB, 288>>>();                                 // 6
    k6_H2<<<dim3(CH/512, BB), 512>>>(b_out1);            // 7
    k6g<<<BB*2, 288>>>();                                // 8
    k8b<<<SS, 128>>>(b_out2, gamma, beta);               // 9
    k7f<<<(BB*CH)/64, 384>>>(x, out);                    // 10
}

// round 11
// speedup vs baseline: 1.6032x; 1.1091x over previous
#include <cuda_runtime.h>
#include <cuda_bf16.h>
#include <mma.h>
#include <math.h>
#include <cstdint>

using namespace nvcuda;

// Problem constants
#define BT   16
#define CH   1024
#define HW   48
#define SP   24
#define SS   576
#define HD   72
#define BB   64
#define BLK  512
#define KTAY 8
#define JJ   16

// ---------------- scratch ----------------
__device__ __align__(16) float g_H2[BB*HD*CH];      // tf32-rounded H2
__device__ __align__(16) float g_xm[BB*CH];
__device__ __align__(16) float g_u [BB*CH];
__device__ __align__(16) float g_t [BB*JJ];         // atomically accumulated
__device__ __align__(16) float g_T [BB*HD*JJ];      // atomically accumulated
__device__ __align__(16) float g_R [BB*HD*JJ];
__device__ __align__(16) float g_M2[HD*HD];
__device__ __align__(16) float g_wv[HD];
__device__ __align__(16) float g_mw2[HD];
__device__ float g_mb2;
__device__ __align__(16) float g_G [HD*HD];
__device__ __align__(16) float g_hs[HD];
__device__ __align__(16) float g_a [SS];
__device__ __align__(16) float g_bsh[SS];
__device__ __align__(16) float g_W1r[80*SS];        // tf32-rounded w_in1, rows 72..79 = 0
__device__ __align__(16) float g_W2r[SS*HD];        // tf32-rounded w_out2

__device__ __forceinline__ float tf32r(float v) { return wmma::__float_to_tf32(v); }

__device__ __forceinline__ void cp_async16(float* smem_dst, const float* gmem_src) {
    unsigned int sa = (unsigned int)__cvta_generic_to_shared(smem_dst);
    asm volatile("cp.async.ca.shared.global [%0], [%1], 16;" :: "r"(sa), "l"(gmem_src));
}

// ---------------- kz: zero accumulators ----------------
__global__ void kz() {
    int i0 = blockIdx.x*512 + threadIdx.x, stride = gridDim.x*512;
    for (int i = i0; i < BB*HD*JJ; i += stride) g_T[i] = 0.f;
    for (int i = i0; i < BB*JJ;    i += stride) g_t[i] = 0.f;
    for (int i = i0; i < HD*HD;    i += stride) g_G[i] = 0.f;
    for (int i = i0; i < HD;       i += stride) g_hs[i] = 0.f;
}

// ---------------- kpr: pre-round weights to tf32 (RN) ----------------
__global__ void kpr(const float* __restrict__ w1, const float* __restrict__ w2o) {
    int i0 = blockIdx.x*512 + threadIdx.x, stride = gridDim.x*512;
    for (int idx = i0; idx < 80*SS; idx += stride) {
        int o = idx / SS;
        g_W1r[idx] = (o < HD) ? tf32r(w1[idx]) : 0.f;
    }
    for (int idx = i0; idx < SS*HD; idx += stride)
        g_W2r[idx] = tf32r(w2o[idx]);
}

// ---------------- kp2 ----------------
__global__ void kp2(const float* __restrict__ w2i, const float* __restrict__ b2i) {
    int t = threadIdx.x;
    if (t < HD) {
        float a = 0.f;
        for (int s = 0; s < SS; s++) a += w2i[s*HD + t];
        g_mw2[t] = a * (1.f/SS);
    }
    if (t == 600) {
        float a = 0.f;
        for (int s = 0; s < SS; s++) a += b2i[s];
        g_mb2 = a * (1.f/SS);
    }
}

// ---------------- kp1 ----------------
__global__ void kp1(const float* __restrict__ w1o, const float* __restrict__ w2i,
                    const float* __restrict__ b2i) {
    int o = blockIdx.x, o2 = threadIdx.x;
    float acc = 0.f;
    for (int s = 0; s < SS; s++) acc = fmaf(w1o[o*SS + s], w2i[s*HD + o2], acc);
    g_M2[o*HD + o2] = acc;
    if (o2 == 0) {
        float a2 = 0.f;
        for (int s = 0; s < SS; s++) a2 = fmaf(w1o[o*SS + s], b2i[s], a2);
        g_wv[o] = a2;
    }
}

// ---------------- K1: H=relu(W1.Xg+b1) tf32 wmma, cp.async A+B, fused xm + T ----------------
// 256 threads / 8 warps; warp w owns n16 block w. K=576 in 12 chunks of 48.
// Epilogue: xm/u, then warp-per-row T/t with register powers + shfl reduction.
__global__ __launch_bounds__(256, 3) void k1_mma(const float* __restrict__ x,
        const float* __restrict__ b1) {
    __shared__ __align__(16) float sm[17472];   // As 80*52 | Bs0 128*52 | Bs1 128*52
    float* As = sm;
    float* Cs = sm;                             // [80][136] alias after loop
    float* xs = sm + 10880;                     // [128] (aliases Bs1)
    float* us = sm + 11008;                     // [128]
    int tid = threadIdx.x, w = tid >> 5, lane = tid & 31;
    int n0 = blockIdx.x << 7;
    int b = n0 >> 10, c0 = n0 & 1023;
    int chunk = b >> 4, bt = b & 15;
    int ty = (chunk >> 1) * SP, tx = (chunk & 1) * SP;
    const float* xb = x + (size_t)(bt*CH + c0) * 2304 + ty*48 + tx;

    wmma::fragment<wmma::accumulator,16,16,8,float> acc[5];
#pragma unroll
    for (int i = 0; i < 5; i++) wmma::fill_fragment(acc[i], 0.f);

    // prefetch B chunk 0
    {
        float* Bn = sm + 4160;
        for (int q = tid; q < 1536; q += 256) {
            int c = q/12, qs = q - c*12;
            int row = (qs >= 6) ? 1 : 0, sxx = (qs - row*6) * 4;
            cp_async16(&Bn[c*52 + row*24 + sxx], xb + (size_t)c*2304 + row*48 + sxx);
        }
        asm volatile("cp.async.commit_group;");
    }

    for (int kc = 0; kc < 12; ++kc) {
        float* Bs = (kc & 1) ? sm + 10816 : sm + 4160;
        __syncthreads();                 // prior mma done reading As / Bn region
        // stage A(kc) via cp.async (pre-rounded, L2-hot)
        for (int q = tid; q < 960; q += 256) {
            int o = q/12, k4 = (q - o*12) * 4;
            cp_async16(&As[o*52 + k4], g_W1r + o*SS + kc*48 + k4);
        }
        asm volatile("cp.async.commit_group;");
        if (kc < 11) {                   // prefetch B(kc+1)
            float* Bn = (kc & 1) ? sm + 4160 : sm + 10816;
            int sy0 = (kc + 1) * 2;
            for (int q = tid; q < 1536; q += 256) {
                int c = q/12, qs = q - c*12;
                int row = (qs >= 6) ? 1 : 0, sxx = (qs - row*6) * 4;
                cp_async16(&Bn[c*52 + row*24 + sxx],
                           xb + (size_t)c*2304 + (sy0 + row)*48 + sxx);
            }
            asm volatile("cp.async.commit_group;");
            asm volatile("cp.async.wait_group 1;");   // B(kc)+A(kc) done, B(kc+1) in flight
        } else {
            asm volatile("cp.async.wait_group 0;");
        }
        __syncthreads();
#pragma unroll
        for (int k8 = 0; k8 < 6; ++k8) {
            wmma::fragment<wmma::matrix_b,16,16,8,wmma::precision::tf32,wmma::col_major> bf;
            wmma::load_matrix_sync(bf, Bs + (w*16)*52 + k8*8, 52);
#pragma unroll
            for (int e = 0; e < 4; e++) bf.x[e] = tf32r(bf.x[e]);
#pragma unroll
            for (int i = 0; i < 5; ++i) {
                wmma::fragment<wmma::matrix_a,16,16,8,wmma::precision::tf32,wmma::row_major> af;
                wmma::load_matrix_sync(af, As + (i*16)*52 + k8*8, 52);
                wmma::mma_sync(acc[i], af, bf, acc[i]);
            }
        }
    }
    __syncthreads();
#pragma unroll
    for (int i = 0; i < 5; ++i)
        wmma::store_matrix_sync(Cs + (i*16)*136 + w*16, acc[i], 136, wmma::mem_row_major);
    __syncthreads();
    // xm/u for these 128 channels
    if (tid < 128) {
        int c = tid;
        float a = g_mb2;
#pragma unroll 8
        for (int o = 0; o < HD; o++) {
            float h = fmaxf(Cs[o*136 + c] + __ldg(&b1[o]), 0.f);
            a = fmaf(g_mw2[o], h, a);
        }
        g_xm[b*CH + c0 + c] = a;
        float uu = expf(-a*a);
        g_u [b*CH + c0 + c] = uu;
        xs[c] = a; us[c] = uu;
    }
    __syncthreads();
    // warp-per-row T (o<72) and t (o==72, ones row): register powers + shfl reduce
    {
        float4 xm4 = *(float4*)&xs[lane << 2];
        float4 u4  = *(float4*)&us[lane << 2];
        int blk = c0 >> 9;
        for (int o = w; o < 73; o += 8) {
            float4 h4;
            if (o < HD) {
                float bias = __ldg(&b1[o]);
                h4 = *(float4*)&Cs[o*136 + (lane << 2)];
                h4.x = fmaxf(h4.x + bias, 0.f); h4.y = fmaxf(h4.y + bias, 0.f);
                h4.z = fmaxf(h4.z + bias, 0.f); h4.w = fmaxf(h4.w + bias, 0.f);
            } else {
                h4 = make_float4(1.f, 1.f, 1.f, 1.f);
            }
            float p0 = u4.x, p1 = u4.y, p2 = u4.z, p3 = u4.w;
            float a[KTAY];
#pragma unroll
            for (int k = 0; k < KTAY; k++) {
                a[k] = fmaf(p0, h4.x, fmaf(p1, h4.y, fmaf(p2, h4.z, p3*h4.w)));
                p0 *= xm4.x; p1 *= xm4.y; p2 *= xm4.z; p3 *= xm4.w;
            }
#pragma unroll
            for (int off = 16; off; off >>= 1)
#pragma unroll
                for (int k = 0; k < KTAY; k++)
                    a[k] += __shfl_xor_sync(0xffffffffu, a[k], off);
            if (lane == 0) {
                if (o < HD) {
#pragma unroll
                    for (int k = 0; k < KTAY; k++)
                        atomicAdd(&g_T[(b*HD + o)*JJ + blk*KTAY + k], a[k]);
                } else {
#pragma unroll
                    for (int k = 0; k < KTAY; k++)
                        atomicAdd(&g_t[(b*2 + blk)*KTAY + k], a[k]);
                }
            }
        }
    }
}

// ---------------- K5: R = M2.T + wv (x) t  (once per b) ----------------
__global__ __launch_bounds__(288) void k5_R() {
    int b = blockIdx.x, tid = threadIdx.x;
    __shared__ float Ts[HD*JJ];
    __shared__ float tb[JJ];
    for (int idx = tid; idx < HD*JJ; idx += 288) Ts[idx] = g_T[b*HD*JJ + idx];
    if (tid < JJ) tb[tid] = g_t[b*JJ + tid];
    __syncthreads();
    for (int idx = tid; idx < HD*JJ; idx += 288) {
        int o = idx / JJ, jj = idx - o*JJ;
        float acc = g_wv[o] * tb[jj];
#pragma unroll 8
        for (int o2 = 0; o2 < HD; o2++)
            acc = fmaf(g_M2[o*HD + o2], Ts[o2*JJ + jj], acc);
        g_R[b*HD*JJ + idx] = acc;
    }
}

// ---------------- K6: H2 from R (written tf32-rounded) ----------------
__global__ __launch_bounds__(512) void k6_H2(const float* __restrict__ b1o) {
    int b = blockIdx.y;
    int d = blockIdx.x * 512 + threadIdx.x;
    int blk = d >> 9;
    int tid = threadIdx.x;
    __shared__ float Rs[HD*JJ];
    __shared__ float tb[JJ];
    __shared__ float bo[HD];
    for (int idx = tid; idx < HD*JJ; idx += 512) Rs[idx] = g_R[b*HD*JJ + idx];
    if (tid < JJ) tb[tid] = g_t[b*JJ + tid];
    if (tid < HD) bo[tid] = b1o[tid];
    __syncthreads();
    float xm = g_xm[b*CH + d];
    float p[KTAY];
    p[0] = 1.f;
#pragma unroll
    for (int k = 1; k < KTAY; k++) p[k] = p[k-1] * (2.f * xm / (float)k);
    float denom = 0.f;
#pragma unroll
    for (int k = 0; k < KTAY; k++) denom = fmaf(p[k], tb[blk*KTAY + k], denom);
    float inv = 1.0f / denom;
    for (int o = 0; o < HD; o++) {
        float acc = 0.f;
#pragma unroll
        for (int k = 0; k < KTAY; k++) acc = fmaf(Rs[o*JJ + blk*KTAY + k], p[k], acc);
        g_H2[(size_t)(b*HD + o)*CH + d] = tf32r(fmaxf(fmaf(acc, inv, bo[o]), 0.f));
    }
}

// ---------------- K6g: Gram (on rounded H2 — matches actual GEMM inputs) ----------------
__global__ __launch_bounds__(288) void k6g() {
    int blk = blockIdx.x;
    int b = blk >> 1, c0 = (blk & 1) << 9;
    int tid = threadIdx.x;
    int i0 = (tid % 24) * 3, j0 = (tid / 24) * 6;
    __shared__ float Hs[HD][65];
    float acc[3][6];
#pragma unroll
    for (int i = 0; i < 3; i++)
#pragma unroll
        for (int j = 0; j < 6; j++) acc[i][j] = 0.f;
    float hs = 0.f;
    for (int cc0 = 0; cc0 < 512; cc0 += 64) {
        for (int idx = tid; idx < HD*64; idx += 288) {
            int o = idx >> 6, cc = idx & 63;
            Hs[o][cc] = g_H2[(size_t)(b*HD + o)*CH + c0 + cc0 + cc];
        }
        __syncthreads();
        if (tid < HD) {
#pragma unroll 16
            for (int cc = 0; cc < 64; cc++) hs += Hs[tid][cc];
        }
#pragma unroll 4
        for (int cc = 0; cc < 64; cc++) {
            float a0 = Hs[i0][cc], a1 = Hs[i0+1][cc], a2 = Hs[i0+2][cc];
#pragma unroll
            for (int jj = 0; jj < 6; ++jj) {
                float bv = Hs[j0+jj][cc];
                acc[0][jj] = fmaf(a0, bv, acc[0][jj]);
                acc[1][jj] = fmaf(a1, bv, acc[1][jj]);
                acc[2][jj] = fmaf(a2, bv, acc[2][jj]);
            }
        }
        __syncthreads();
    }
#pragma unroll
    for (int ii = 0; ii < 3; ii++)
#pragma unroll
        for (int jj = 0; jj < 6; jj++)
            atomicAdd(&g_G[(i0+ii)*HD + j0+jj], acc[ii][jj]);
    if (tid < HD) atomicAdd(&g_hs[tid], hs);
}

// ---------------- K8b: analytic BN stats (rounded w2o for consistency) ----------------
__global__ __launch_bounds__(128) void k8b(const float* __restrict__ b2o,
        const float* __restrict__ gamma, const float* __restrict__ beta) {
    int s = blockIdx.x, t = threadIdx.x;
    __shared__ float rq[128], rd[128];
    float q = 0.f, d = 0.f;
    if (t < HD) {
        float wt = g_W2r[s*HD + t];
        float v = 0.f;
        for (int o2 = 0; o2 < HD; ++o2)
            v = fmaf(g_G[t*HD + o2], g_W2r[s*HD + o2], v);
        q = wt * v;
        d = wt * g_hs[t];
    }
    rq[t] = q; rd[t] = d;
    __syncthreads();
    for (int st = 64; st > 0; st >>= 1) {
        if (t < st) { rq[t] += rq[t+st]; rd[t] += rd[t+st]; }
        __syncthreads();
    }
    if (t == 0) {
        const float N = (float)(BB*CH);
        float bias = b2o[s];
        float dot = rd[0];
        float mu = dot / N + bias;
        float esq = rq[0]/N + 2.f*bias*dot/N + bias*bias;
        float var = esq - mu*mu;
        float a = rsqrtf(var + 1e-5f) * gamma[s];
        g_a  [s] = 0.25f * a;
        g_bsh[s] = 0.25f * (beta[s] + a*(bias - mu));
    }
}

// ---------------- K7f: O = W2r.H2 (tf32) + BN + scatter + relu, pipelined ----------------
// N=64 channels/block (grid 1024), 384 threads / 12 warps. Separate Os region so
// the A(p+1) cp.async overlaps the scatter of pass p. Warp: mg=w>>1 m16 tile, ng=w&1 n32.
__global__ __launch_bounds__(384, 3) void k7f(const float* __restrict__ x,
        float* __restrict__ out) {
    __shared__ __align__(16) float Bs[HD*68];     // [o][c] pitch 68
    __shared__ __align__(16) float As[96*76];     // [sl][o] pitch 76
    __shared__ __align__(16) float Os[64*100];    // [c][sl] pitch 100
    int tid = threadIdx.x, w = tid >> 5;
    int mg = w >> 1, ng = w & 1;
    int n0 = blockIdx.x << 6;
    int b = n0 >> 10, c0 = n0 & 1023;

    // prologue: stage B + A(0) via cp.async
    for (int q = tid; q < HD*16; q += 384) {
        int o = q >> 4, c4 = (q & 15) * 4;
        cp_async16(&Bs[o*68 + c4], g_H2 + (size_t)(b*HD + o)*CH + c0 + c4);
    }
    for (int q = tid; q < 96*18; q += 384) {
        int sl = q / 18, o4 = (q - sl*18) * 4;
        cp_async16(&As[sl*76 + o4], g_W2r + (size_t)sl*HD + o4);
    }
    asm volatile("cp.async.commit_group;");
    asm volatile("cp.async.wait_group 0;");
    __syncthreads();

    int chunk = b >> 4, bt = b & 15;
    int ty = (chunk >> 1)*SP, tx = (chunk & 1)*SP;
    const float* xb = x   + (size_t)(bt*CH + c0)*2304 + ty*48 + tx;
    float*       ob = out + (size_t)(bt*CH + c0)*2304 + ty*48 + tx;

    for (int p = 0; p < 6; ++p) {
        wmma::fragment<wmma::accumulator,16,16,8,float> acc[2];
        wmma::fill_fragment(acc[0], 0.f);
        wmma::fill_fragment(acc[1], 0.f);
#pragma unroll
        for (int k8 = 0; k8 < 9; ++k8) {
            wmma::fragment<wmma::matrix_b,16,16,8,wmma::precision::tf32,wmma::row_major> bf[2];
            wmma::load_matrix_sync(bf[0], Bs + (k8*8)*68 + ng*32,      68);
            wmma::load_matrix_sync(bf[1], Bs + (k8*8)*68 + ng*32 + 16, 68);
            wmma::fragment<wmma::matrix_a,16,16,8,wmma::precision::tf32,wmma::row_major> af;
            wmma::load_matrix_sync(af, As + (mg*16)*76 + k8*8, 76);
            wmma::mma_sync(acc[0], af, bf[0], acc[0]);
            wmma::mma_sync(acc[1], af, bf[1], acc[1]);
        }
        __syncthreads();   // mma done reading As; prev scatter done reading Os
#pragma unroll
        for (int cf = 0; cf < 2; ++cf)
            wmma::store_matrix_sync(Os + (ng*32 + cf*16)*100 + mg*16,
                                    acc[cf], 100, wmma::mem_col_major);
        if (p < 5) {       // stage A(p+1); overlaps the scatter below
            for (int q = tid; q < 96*18; q += 384) {
                int sl = q / 18, o4 = (q - sl*18) * 4;
                cp_async16(&As[sl*76 + o4], g_W2r + (size_t)((p+1)*96 + sl)*HD + o4);
            }
            asm volatile("cp.async.commit_group;");
        }
        __syncthreads();   // Os stores visible
        for (int idx = tid; idx < 1536; idx += 384) {
            int sx4 = idx % 6;
            int t2  = idx / 6;
            int syl = t2 & 3;
            int c   = t2 >> 2;
            int sl  = syl*24 + sx4*4;
            int s0  = p*96 + sl;
            float4 v  = *(float4*)&Os[c*100 + sl];
            float4 av = *(const float4*)&g_a[s0];
            float4 bv = *(const float4*)&g_bsh[s0];
            size_t ga = (size_t)c*2304 + (p*4 + syl)*48 + sx4*4;
            float4 xv = *(const float4*)(xb + ga);
            float4 r;
            r.x = fmaxf(xv.x + fmaf(v.x, av.x, bv.x), 0.f);
            r.y = fmaxf(xv.y + fmaf(v.y, av.y, bv.y), 0.f);
            r.z = fmaxf(xv.z + fmaf(v.z, av.z, bv.z), 0.f);
            r.w = fmaxf(xv.w + fmaf(v.w, av.w, bv.w), 0.f);
            *(float4*)(ob + ga) = r;
        }
        if (p < 5) {
            asm volatile("cp.async.wait_group 0;");
            __syncthreads();   // As(p+1) ready
        }
    }
}

// ---------------- launch ----------------
extern "C" void kernel_launch(void* const* d_in, const int* in_sizes, int n_in,
                              void* d_out, int out_size) {
    (void)in_sizes; (void)n_in; (void)out_size;
    const float* x      = (const float*)d_in[0];
    const float* w_in1  = (const float*)d_in[1];
    const float* b_in1  = (const float*)d_in[2];
    const float* w_in2  = (const float*)d_in[3];
    const float* b_in2  = (const float*)d_in[4];
    const float* w_out1 = (const float*)d_in[5];
    const float* b_out1 = (const float*)d_in[6];
    const float* w_out2 = (const float*)d_in[7];
    const float* b_out2 = (const float*)d_in[8];
    const float* gamma  = (const float*)d_in[9];
    const float* beta   = (const float*)d_in[10];
    float* out = (float*)d_out;

    kz <<<64, 512>>>();                                  // 1
    kp2<<<1, 640>>>(w_in2, b_in2);                       // 2
    kpr<<<64, 512>>>(w_in1, w_out2);                     // 3
    k1_mma<<<(BB*CH)/128, 256>>>(x, b_in1);              // 4  <- profiled slot
    kp1<<<HD, HD>>>(w_out1, w_in2, b_in2);               // 5
    k5_R<<<BB, 288>>>();                                 // 6
    k6_H2<<<dim3(CH/512, BB), 512>>>(b_out1);            // 7
    k6g<<<BB*2, 288>>>();                                // 8
    k8b<<<SS, 128>>>(b_out2, gamma, beta);               // 9
    k7f<<<(BB*CH)/64, 384>>>(x, out);                    // 10
}